// round 2
// baseline (speedup 1.0000x reference)
#include <cuda_runtime.h>

// ---------------------------------------------------------------------------
// GraphConvLSTM on GB300 — Round 2: fully fused persistent-per-batch kernel.
// One block = one batch element: h, W, gate-inputs resident in smem/regs for
// all 100 timesteps. GEMM inner loop uses packed fma.rn.f32x2 (FFMA2).
// ---------------------------------------------------------------------------

#define BATCH   512
#define INDIM   256
#define HDIM    128
#define TSTEPS  100
#define NNODES  22
#define MROWS   24            // padded rows for GEMM tiling

// -------------------- scratch (device globals, no allocs) ------------------
__device__ float g_xg[4 * BATCH * HDIM];        // precomputed gate inputs (4,B,H)

// -------------------- normalized adjacency (baked constants) ---------------
__constant__ int c_cnt[NNODES] = {13,4,4,5,4,4,5,4,4,13,4,4,5,4,4,5,4,4,4,4,4,4};
__constant__ int c_nbr[NNODES][13] = {
    {1,2,3,4,5,6,7,8,9,10,11,12,15},
    {0,4,7,10, 0,0,0,0,0,0,0,0,0},
    {0,5,8,11, 0,0,0,0,0,0,0,0,0},
    {0,6,9,12,15, 0,0,0,0,0,0,0,0},
    {0,1,7,10, 0,0,0,0,0,0,0,0,0},
    {0,2,8,11, 0,0,0,0,0,0,0,0,0},
    {0,3,9,12,15, 0,0,0,0,0,0,0,0},
    {0,1,4,10, 0,0,0,0,0,0,0,0,0},
    {0,2,5,11, 0,0,0,0,0,0,0,0,0},
    {0,3,6,12,15,13,14,16,17,18,19,20,21},
    {0,1,4,7, 0,0,0,0,0,0,0,0,0},
    {0,2,5,8, 0,0,0,0,0,0,0,0,0},
    {0,3,6,9,15, 0,0,0,0,0,0,0,0},
    {9,16,18,20, 0,0,0,0,0,0,0,0,0},
    {9,17,19,21, 0,0,0,0,0,0,0,0,0},
    {0,3,6,9,12, 0,0,0,0,0,0,0,0},
    {9,13,18,20, 0,0,0,0,0,0,0,0,0},
    {9,14,19,21, 0,0,0,0,0,0,0,0,0},
    {9,13,16,20, 0,0,0,0,0,0,0,0,0},
    {9,14,17,21, 0,0,0,0,0,0,0,0,0},
    {9,13,16,18, 0,0,0,0,0,0,0,0,0},
    {9,14,17,19, 0,0,0,0,0,0,0,0,0}
};
__constant__ float c_dinv[NNODES] = {
    0.2773500979f, 0.5f, 0.5f, 0.4472135955f, 0.5f, 0.5f, 0.4472135955f, 0.5f, 0.5f,
    0.2773500979f, 0.5f, 0.5f, 0.4472135955f, 0.5f, 0.5f, 0.4472135955f,
    0.5f, 0.5f, 0.5f, 0.5f, 0.5f, 0.5f
};

// -------------------- packed f32x2 helpers ----------------------------------
__device__ __forceinline__ unsigned long long bcast2(float x) {
    unsigned long long r;
    asm("mov.b64 %0, {%1, %1};" : "=l"(r) : "f"(x));
    return r;
}
__device__ __forceinline__ void fma2(unsigned long long& d,
                                     unsigned long long a, unsigned long long b) {
    asm("fma.rn.f32x2 %0, %1, %2, %0;" : "+l"(d) : "l"(a), "l"(b));
}
__device__ __forceinline__ float2 unpk2(unsigned long long v) {
    float2 f;
    asm("mov.b64 {%0, %1}, %2;" : "=f"(f.x), "=f"(f.y) : "l"(v));
    return f;
}

// -------------------- math helpers (saturation-safe) ------------------------
__device__ __forceinline__ float fsig(float x) {
    return __fdividef(1.0f, 1.0f + __expf(-x));
}
__device__ __forceinline__ float ftanh_(float x) {
    return 1.0f - __fdividef(2.0f, __expf(2.0f * x) + 1.0f);
}

// -------------------- gate projection: xg[g] = x @ W_g^T + b_g -------------
__global__ __launch_bounds__(128) void gate_kernel(
    const float* __restrict__ x,
    const float* __restrict__ wi, const float* __restrict__ bi,
    const float* __restrict__ wf, const float* __restrict__ bf,
    const float* __restrict__ wo, const float* __restrict__ bo,
    const float* __restrict__ wc, const float* __restrict__ bc)
{
    __shared__ float xs[16 * INDIM];
    __shared__ float ws[32 * 129];

    int tid  = threadIdx.x;
    int gate = blockIdx.y;
    const float* w    = (gate == 0) ? wi : (gate == 1) ? wf : (gate == 2) ? wo : wc;
    const float* bias = (gate == 0) ? bi : (gate == 1) ? bf : (gate == 2) ? bo : bc;
    int b0 = blockIdx.x * 16;

    for (int i = tid; i < 16 * INDIM; i += 128) xs[i] = x[b0 * INDIM + i];

    float acc[16];
#pragma unroll
    for (int bb = 0; bb < 16; bb++) acc[bb] = 0.f;

    for (int k0 = 0; k0 < INDIM; k0 += 32) {
        __syncthreads();
        for (int i = tid; i < 128 * 32; i += 128) {
            int j = i >> 5, k = i & 31;
            ws[k * 129 + j] = w[j * INDIM + k0 + k];
        }
        __syncthreads();
#pragma unroll 8
        for (int k = 0; k < 32; k++) {
            float wv = ws[k * 129 + tid];
#pragma unroll
            for (int bb = 0; bb < 16; bb++)
                acc[bb] += xs[bb * INDIM + k0 + k] * wv;
        }
    }
    float bv = bias[tid];
#pragma unroll
    for (int bb = 0; bb < 16; bb++)
        g_xg[(gate * BATCH + b0 + bb) * HDIM + tid] = acc[bb] + bv;
}

// -------------------- fused per-batch recurrence -----------------------------
// grid = 512 blocks (1 per batch), 128 threads.
// dyn smem: ws[128*128] | ms[24*128] | hs[24*128]   (88 KB)
// thread microtile: 3 rows x 8 cols (16 col-groups x 8 row-groups).
__global__ __launch_bounds__(128) void fused_kernel(
    const float* __restrict__ gw,
    const float* __restrict__ gb,
    float* __restrict__ out)
{
    extern __shared__ float dyn[];
    float* ws = dyn;                         // 16384 floats
    float* ms = dyn + HDIM * HDIM;           // 3072
    float* hs = ms + MROWS * HDIM;           // 3072

    const int b   = blockIdx.x;
    const int tid = threadIdx.x;
    const int jt  = tid & 15;                // col group (8 cols)
    const int rg  = tid >> 4;                // row group (3 rows)
    const int j0  = jt * 8;

    // ---- load W once (coalesced float4) ----
    {
        const float4* g4 = reinterpret_cast<const float4*>(gw);
        float4*       w4 = reinterpret_cast<float4*>(ws);
        for (int i = tid; i < HDIM * HDIM / 4; i += 128) w4[i] = g4[i];
    }
    // ---- zero h ----
    {
        float4 z = make_float4(0.f, 0.f, 0.f, 0.f);
        float4* h4 = reinterpret_cast<float4*>(hs);
        for (int i = tid; i < MROWS * HDIM / 4; i += 128) h4[i] = z;
    }

    // ---- per-thread gate inputs with gcn bias folded in (registers) ----
    float xi[8], xf[8], xo[8], xc[8];
#pragma unroll
    for (int q = 0; q < 8; q++) {
        int j = j0 + q;
        float gbv = gb[j];
        xi[q] = g_xg[(0 * BATCH + b) * HDIM + j] + gbv;
        xf[q] = g_xg[(1 * BATCH + b) * HDIM + j] + gbv;
        xo[q] = g_xg[(2 * BATCH + b) * HDIM + j] + gbv;
        xc[q] = g_xg[(3 * BATCH + b) * HDIM + j] + gbv;
    }

    float c[3][8];
#pragma unroll
    for (int i = 0; i < 3; i++)
#pragma unroll
        for (int q = 0; q < 8; q++) c[i][q] = 0.f;

    __syncthreads();

    const float4* msv = reinterpret_cast<const float4*>(ms);

    for (int t = 0; t < TSTEPS; t++) {
        // ---- msg = A_norm @ h (from smem) : 24 rows x 128 cols ----
#pragma unroll
        for (int p = 0; p < 6; p++) {
            int id  = p * 128 + tid;
            int row = id >> 5;               // warp-uniform
            int jv  = (id & 31) << 2;
            float4 a = make_float4(0.f, 0.f, 0.f, 0.f);
            if (row < NNODES) {
                int   cnt = c_cnt[row];
                float dm  = c_dinv[row];
                for (int q = 0; q < cnt; q++) {
                    int   n  = c_nbr[row][q];
                    float cf = dm * c_dinv[n];
                    float4 hv = *reinterpret_cast<const float4*>(hs + n * HDIM + jv);
                    a.x += cf * hv.x; a.y += cf * hv.y;
                    a.z += cf * hv.z; a.w += cf * hv.w;
                }
            }
            *reinterpret_cast<float4*>(ms + row * HDIM + jv) = a;
        }
        __syncthreads();

        // ---- GEMM: acc(3x8) = msg(3x128) @ W(128x8)  via FFMA2 ----
        unsigned long long acc[3][4];
#pragma unroll
        for (int i = 0; i < 3; i++)
#pragma unroll
            for (int q = 0; q < 4; q++) acc[i][q] = 0ull;

#pragma unroll 4
        for (int kq = 0; kq < 32; kq++) {
            float4 m0 = msv[(rg * 3 + 0) * 32 + kq];
            float4 m1 = msv[(rg * 3 + 1) * 32 + kq];
            float4 m2 = msv[(rg * 3 + 2) * 32 + kq];
            float m0a[4] = {m0.x, m0.y, m0.z, m0.w};
            float m1a[4] = {m1.x, m1.y, m1.z, m1.w};
            float m2a[4] = {m2.x, m2.y, m2.z, m2.w};
#pragma unroll
            for (int kk = 0; kk < 4; kk++) {
                const ulonglong2* wp = reinterpret_cast<const ulonglong2*>(
                    ws + ((kq * 4 + kk) << 7) + j0);
                ulonglong2 wa = wp[0];   // cols j0..j0+3
                ulonglong2 wb = wp[1];   // cols j0+4..j0+7
                unsigned long long p;
                p = bcast2(m0a[kk]);
                fma2(acc[0][0], p, wa.x); fma2(acc[0][1], p, wa.y);
                fma2(acc[0][2], p, wb.x); fma2(acc[0][3], p, wb.y);
                p = bcast2(m1a[kk]);
                fma2(acc[1][0], p, wa.x); fma2(acc[1][1], p, wa.y);
                fma2(acc[1][2], p, wb.x); fma2(acc[1][3], p, wb.y);
                p = bcast2(m2a[kk]);
                fma2(acc[2][0], p, wa.x); fma2(acc[2][1], p, wa.y);
                fma2(acc[2][2], p, wb.x); fma2(acc[2][3], p, wb.y);
            }
        }

        // ---- LSTM epilogue: update c (regs), h (smem), write out ----
#pragma unroll
        for (int i = 0; i < 3; i++) {
            int r = rg * 3 + i;
            if (r < NNODES) {
                float2 t01 = unpk2(acc[i][0]);
                float2 t23 = unpk2(acc[i][1]);
                float2 t45 = unpk2(acc[i][2]);
                float2 t67 = unpk2(acc[i][3]);
                float g[8] = {t01.x, t01.y, t23.x, t23.y, t45.x, t45.y, t67.x, t67.y};
                float hv[8];
#pragma unroll
                for (int q = 0; q < 8; q++) {
                    float gg = g[q];
                    float it = fsig(xi[q] + gg);
                    float ft = fsig(xf[q] + gg);
                    float ot = fsig(xo[q] + gg);
                    float ct = ftanh_(xc[q] + gg);
                    float cn = ft * c[i][q] + it * ct;
                    c[i][q] = cn;
                    hv[q] = ot * ftanh_(cn);
                }
                float4 h0 = make_float4(hv[0], hv[1], hv[2], hv[3]);
                float4 h1 = make_float4(hv[4], hv[5], hv[6], hv[7]);
                *reinterpret_cast<float4*>(hs + r * HDIM + j0)     = h0;
                *reinterpret_cast<float4*>(hs + r * HDIM + j0 + 4) = h1;
                float4* op = reinterpret_cast<float4*>(
                    out + (((size_t)b * TSTEPS + t) * NNODES + r) * HDIM + j0);
                op[0] = h0;
                op[1] = h1;
            }
        }
        __syncthreads();   // h writes visible before next step's msg reads
    }
}

// -------------------- launch -------------------------------------------------
extern "C" void kernel_launch(void* const* d_in, const int* in_sizes, int n_in,
                              void* d_out, int out_size) {
    (void)in_sizes; (void)n_in; (void)out_size;
    const float* x     = (const float*)d_in[0];
    const float* wi_w  = (const float*)d_in[1];
    const float* wi_b  = (const float*)d_in[2];
    const float* wf_w  = (const float*)d_in[3];
    const float* wf_b  = (const float*)d_in[4];
    const float* wo_w  = (const float*)d_in[5];
    const float* wo_b  = (const float*)d_in[6];
    const float* wc_w  = (const float*)d_in[7];
    const float* wc_b  = (const float*)d_in[8];
    const float* gcn_w = (const float*)d_in[9];
    const float* gcn_b = (const float*)d_in[10];
    float* out = (float*)d_out;

    const int smem_bytes = (HDIM * HDIM + 2 * MROWS * HDIM) * sizeof(float); // 88 KB
    cudaFuncSetAttribute(fused_kernel,
                         cudaFuncAttributeMaxDynamicSharedMemorySize, smem_bytes);

    gate_kernel<<<dim3(BATCH / 16, 4), 128>>>(x, wi_w, wi_b, wf_w, wf_b,
                                              wo_w, wo_b, wc_w, wc_b);
    fused_kernel<<<BATCH, 128, smem_bytes>>>(gcn_w, gcn_b, out);
}

// round 3
// speedup vs baseline: 1.0776x; 1.0776x over previous
#include <cuda_runtime.h>

// ---------------------------------------------------------------------------
// GraphConvLSTM on GB300 — Round 3: fused persistent kernel, 4 batches/block.
// grid = 128 blocks (single wave on 148 SMs), 512 threads = 4 groups x 128.
// Each group runs one batch's full 100-step recurrence with its own named
// barrier; W (64 KB) staged once per block and shared by all groups.
// GEMM inner loop uses packed fma.rn.f32x2 (FFMA2).
// ---------------------------------------------------------------------------

#define BATCH   512
#define INDIM   256
#define HDIM    128
#define TSTEPS  100
#define NNODES  22
#define MROWS   24            // padded rows for GEMM tiling
#define GROUPS  4             // batches per block

// -------------------- scratch (device globals, no allocs) ------------------
__device__ float g_xg[4 * BATCH * HDIM];        // precomputed gate inputs (4,B,H)

// -------------------- normalized adjacency (baked constants) ---------------
__constant__ int c_cnt[NNODES] = {13,4,4,5,4,4,5,4,4,13,4,4,5,4,4,5,4,4,4,4,4,4};
__constant__ int c_nbr[NNODES][13] = {
    {1,2,3,4,5,6,7,8,9,10,11,12,15},
    {0,4,7,10, 0,0,0,0,0,0,0,0,0},
    {0,5,8,11, 0,0,0,0,0,0,0,0,0},
    {0,6,9,12,15, 0,0,0,0,0,0,0,0},
    {0,1,7,10, 0,0,0,0,0,0,0,0,0},
    {0,2,8,11, 0,0,0,0,0,0,0,0,0},
    {0,3,9,12,15, 0,0,0,0,0,0,0,0},
    {0,1,4,10, 0,0,0,0,0,0,0,0,0},
    {0,2,5,11, 0,0,0,0,0,0,0,0,0},
    {0,3,6,12,15,13,14,16,17,18,19,20,21},
    {0,1,4,7, 0,0,0,0,0,0,0,0,0},
    {0,2,5,8, 0,0,0,0,0,0,0,0,0},
    {0,3,6,9,15, 0,0,0,0,0,0,0,0},
    {9,16,18,20, 0,0,0,0,0,0,0,0,0},
    {9,17,19,21, 0,0,0,0,0,0,0,0,0},
    {0,3,6,9,12, 0,0,0,0,0,0,0,0},
    {9,13,18,20, 0,0,0,0,0,0,0,0,0},
    {9,14,19,21, 0,0,0,0,0,0,0,0,0},
    {9,13,16,20, 0,0,0,0,0,0,0,0,0},
    {9,14,17,21, 0,0,0,0,0,0,0,0,0},
    {9,13,16,18, 0,0,0,0,0,0,0,0,0},
    {9,14,17,19, 0,0,0,0,0,0,0,0,0}
};
__constant__ float c_dinv[NNODES] = {
    0.2773500979f, 0.5f, 0.5f, 0.4472135955f, 0.5f, 0.5f, 0.4472135955f, 0.5f, 0.5f,
    0.2773500979f, 0.5f, 0.5f, 0.4472135955f, 0.5f, 0.5f, 0.4472135955f,
    0.5f, 0.5f, 0.5f, 0.5f, 0.5f, 0.5f
};

// -------------------- packed f32x2 helpers ----------------------------------
__device__ __forceinline__ unsigned long long bcast2(float x) {
    unsigned long long r;
    asm("mov.b64 %0, {%1, %1};" : "=l"(r) : "f"(x));
    return r;
}
__device__ __forceinline__ void fma2(unsigned long long& d,
                                     unsigned long long a, unsigned long long b) {
    asm("fma.rn.f32x2 %0, %1, %2, %0;" : "+l"(d) : "l"(a), "l"(b));
}
__device__ __forceinline__ float2 unpk2(unsigned long long v) {
    float2 f;
    asm("mov.b64 {%0, %1}, %2;" : "=f"(f.x), "=f"(f.y) : "l"(v));
    return f;
}

// -------------------- math helpers (saturation-safe) ------------------------
__device__ __forceinline__ float fsig(float x) {
    return __fdividef(1.0f, 1.0f + __expf(-x));
}
__device__ __forceinline__ float ftanh_(float x) {
    return 1.0f - __fdividef(2.0f, __expf(2.0f * x) + 1.0f);
}

// -------------------- gate projection: xg[g] = x @ W_g^T + b_g -------------
__global__ __launch_bounds__(128) void gate_kernel(
    const float* __restrict__ x,
    const float* __restrict__ wi, const float* __restrict__ bi,
    const float* __restrict__ wf, const float* __restrict__ bf,
    const float* __restrict__ wo, const float* __restrict__ bo,
    const float* __restrict__ wc, const float* __restrict__ bc)
{
    __shared__ float xs[16 * INDIM];
    __shared__ float ws[32 * 129];

    int tid  = threadIdx.x;
    int gate = blockIdx.y;
    const float* w    = (gate == 0) ? wi : (gate == 1) ? wf : (gate == 2) ? wo : wc;
    const float* bias = (gate == 0) ? bi : (gate == 1) ? bf : (gate == 2) ? bo : bc;
    int b0 = blockIdx.x * 16;

    for (int i = tid; i < 16 * INDIM; i += 128) xs[i] = x[b0 * INDIM + i];

    float acc[16];
#pragma unroll
    for (int bb = 0; bb < 16; bb++) acc[bb] = 0.f;

    for (int k0 = 0; k0 < INDIM; k0 += 32) {
        __syncthreads();
        for (int i = tid; i < 128 * 32; i += 128) {
            int j = i >> 5, k = i & 31;
            ws[k * 129 + j] = w[j * INDIM + k0 + k];
        }
        __syncthreads();
#pragma unroll 8
        for (int k = 0; k < 32; k++) {
            float wv = ws[k * 129 + tid];
#pragma unroll
            for (int bb = 0; bb < 16; bb++)
                acc[bb] += xs[bb * INDIM + k0 + k] * wv;
        }
    }
    float bv = bias[tid];
#pragma unroll
    for (int bb = 0; bb < 16; bb++)
        g_xg[(gate * BATCH + b0 + bb) * HDIM + tid] = acc[bb] + bv;
}

// -------------------- fused recurrence: 4 batches per block ------------------
// dyn smem: ws[128*128] | ms[4][24*128] | hs[4][24*128]   (160 KB)
// group g = threads [128g, 128g+128): one batch, private named barrier g+1.
__global__ __launch_bounds__(512, 1) void fused_kernel(
    const float* __restrict__ gw,
    const float* __restrict__ gb,
    float* __restrict__ out)
{
    extern __shared__ float dyn[];
    float* ws = dyn;                                   // 16384 floats (64 KB)

    const int tid  = threadIdx.x;
    const int g    = tid >> 7;          // batch group 0..3
    const int ltid = tid & 127;         // thread within group
    const int b    = blockIdx.x * GROUPS + g;

    float* ms = dyn + HDIM * HDIM + g * (MROWS * HDIM);
    float* hs = dyn + HDIM * HDIM + GROUPS * (MROWS * HDIM) + g * (MROWS * HDIM);

    const int jt = ltid & 15;           // col group (8 cols)
    const int rg = ltid >> 4;           // row group (3 rows)
    const int j0 = jt * 8;

    // ---- block-cooperative: load W once, zero all hs ----
    {
        const float4* g4 = reinterpret_cast<const float4*>(gw);
        float4*       w4 = reinterpret_cast<float4*>(ws);
#pragma unroll
        for (int i = tid; i < HDIM * HDIM / 4; i += 512) w4[i] = g4[i];

        float4 z = make_float4(0.f, 0.f, 0.f, 0.f);
        float4* h4 = reinterpret_cast<float4*>(dyn + HDIM * HDIM + GROUPS * (MROWS * HDIM));
#pragma unroll
        for (int i = tid; i < GROUPS * MROWS * HDIM / 4; i += 512) h4[i] = z;
    }

    // ---- per-thread gate inputs with gcn bias folded in (registers) ----
    float xi[8], xf[8], xo[8], xc[8];
#pragma unroll
    for (int q = 0; q < 8; q++) {
        int j = j0 + q;
        float gbv = gb[j];
        xi[q] = g_xg[(0 * BATCH + b) * HDIM + j] + gbv;
        xf[q] = g_xg[(1 * BATCH + b) * HDIM + j] + gbv;
        xo[q] = g_xg[(2 * BATCH + b) * HDIM + j] + gbv;
        xc[q] = g_xg[(3 * BATCH + b) * HDIM + j] + gbv;
    }

    float c[3][8];
#pragma unroll
    for (int i = 0; i < 3; i++)
#pragma unroll
        for (int q = 0; q < 8; q++) c[i][q] = 0.f;

    __syncthreads();    // W + hs ready for everyone; groups free-run after this

    const float4* msv = reinterpret_cast<const float4*>(ms);
    const int bar = g + 1;

    for (int t = 0; t < TSTEPS; t++) {
        // ---- msg = A_norm @ h (smem -> smem), 24 rows x 128 cols ----
#pragma unroll
        for (int p = 0; p < 6; p++) {
            int id  = p * 128 + ltid;
            int row = id >> 5;               // warp-uniform
            int jv  = (id & 31) << 2;
            float4 a = make_float4(0.f, 0.f, 0.f, 0.f);
            if (row < NNODES) {
                int   cnt = c_cnt[row];
                float dm  = c_dinv[row];
                for (int q = 0; q < cnt; q++) {
                    int   n  = c_nbr[row][q];
                    float cf = dm * c_dinv[n];
                    float4 hv = *reinterpret_cast<const float4*>(hs + n * HDIM + jv);
                    a.x += cf * hv.x; a.y += cf * hv.y;
                    a.z += cf * hv.z; a.w += cf * hv.w;
                }
            }
            *reinterpret_cast<float4*>(ms + row * HDIM + jv) = a;
        }
        asm volatile("bar.sync %0, 128;" :: "r"(bar) : "memory");

        // ---- GEMM: acc(3x8) = msg(3x128) @ W(128x8) via FFMA2 ----
        unsigned long long acc[3][4];
#pragma unroll
        for (int i = 0; i < 3; i++)
#pragma unroll
            for (int q = 0; q < 4; q++) acc[i][q] = 0ull;

#pragma unroll 4
        for (int kq = 0; kq < 32; kq++) {
            float4 m0 = msv[(rg * 3 + 0) * 32 + kq];
            float4 m1 = msv[(rg * 3 + 1) * 32 + kq];
            float4 m2 = msv[(rg * 3 + 2) * 32 + kq];
            float m0a[4] = {m0.x, m0.y, m0.z, m0.w};
            float m1a[4] = {m1.x, m1.y, m1.z, m1.w};
            float m2a[4] = {m2.x, m2.y, m2.z, m2.w};
#pragma unroll
            for (int kk = 0; kk < 4; kk++) {
                const ulonglong2* wp = reinterpret_cast<const ulonglong2*>(
                    ws + ((kq * 4 + kk) << 7) + j0);
                ulonglong2 wa = wp[0];   // cols j0..j0+3
                ulonglong2 wb = wp[1];   // cols j0+4..j0+7
                unsigned long long p;
                p = bcast2(m0a[kk]);
                fma2(acc[0][0], p, wa.x); fma2(acc[0][1], p, wa.y);
                fma2(acc[0][2], p, wb.x); fma2(acc[0][3], p, wb.y);
                p = bcast2(m1a[kk]);
                fma2(acc[1][0], p, wa.x); fma2(acc[1][1], p, wa.y);
                fma2(acc[1][2], p, wb.x); fma2(acc[1][3], p, wb.y);
                p = bcast2(m2a[kk]);
                fma2(acc[2][0], p, wa.x); fma2(acc[2][1], p, wa.y);
                fma2(acc[2][2], p, wb.x); fma2(acc[2][3], p, wb.y);
            }
        }

        // ---- LSTM epilogue: update c (regs), h (smem), write out ----
#pragma unroll
        for (int i = 0; i < 3; i++) {
            int r = rg * 3 + i;
            if (r < NNODES) {
                float2 t01 = unpk2(acc[i][0]);
                float2 t23 = unpk2(acc[i][1]);
                float2 t45 = unpk2(acc[i][2]);
                float2 t67 = unpk2(acc[i][3]);
                float gv[8] = {t01.x, t01.y, t23.x, t23.y, t45.x, t45.y, t67.x, t67.y};
                float hv[8];
#pragma unroll
                for (int q = 0; q < 8; q++) {
                    float gg = gv[q];
                    float it = fsig(xi[q] + gg);
                    float ft = fsig(xf[q] + gg);
                    float ot = fsig(xo[q] + gg);
                    float ct = ftanh_(xc[q] + gg);
                    float cn = ft * c[i][q] + it * ct;
                    c[i][q] = cn;
                    hv[q] = ot * ftanh_(cn);
                }
                float4 h0 = make_float4(hv[0], hv[1], hv[2], hv[3]);
                float4 h1 = make_float4(hv[4], hv[5], hv[6], hv[7]);
                *reinterpret_cast<float4*>(hs + r * HDIM + j0)     = h0;
                *reinterpret_cast<float4*>(hs + r * HDIM + j0 + 4) = h1;
                float4* op = reinterpret_cast<float4*>(
                    out + (((size_t)b * TSTEPS + t) * NNODES + r) * HDIM + j0);
                op[0] = h0;
                op[1] = h1;
            }
        }
        asm volatile("bar.sync %0, 128;" :: "r"(bar) : "memory");
    }
}

// -------------------- launch -------------------------------------------------
extern "C" void kernel_launch(void* const* d_in, const int* in_sizes, int n_in,
                              void* d_out, int out_size) {
    (void)in_sizes; (void)n_in; (void)out_size;
    const float* x     = (const float*)d_in[0];
    const float* wi_w  = (const float*)d_in[1];
    const float* wi_b  = (const float*)d_in[2];
    const float* wf_w  = (const float*)d_in[3];
    const float* wf_b  = (const float*)d_in[4];
    const float* wo_w  = (const float*)d_in[5];
    const float* wo_b  = (const float*)d_in[6];
    const float* wc_w  = (const float*)d_in[7];
    const float* wc_b  = (const float*)d_in[8];
    const float* gcn_w = (const float*)d_in[9];
    const float* gcn_b = (const float*)d_in[10];
    float* out = (float*)d_out;

    const int smem_bytes =
        (HDIM * HDIM + 2 * GROUPS * MROWS * HDIM) * sizeof(float);   // 160 KB
    cudaFuncSetAttribute(fused_kernel,
                         cudaFuncAttributeMaxDynamicSharedMemorySize, smem_bytes);

    gate_kernel<<<dim3(BATCH / 16, 4), 128>>>(x, wi_w, wi_b, wf_w, wf_b,
                                              wo_w, wo_b, wc_w, wc_b);
    fused_kernel<<<BATCH / GROUPS, 512, smem_bytes>>>(gcn_w, gcn_b, out);
}

// round 4
// speedup vs baseline: 1.5826x; 1.4687x over previous
#include <cuda_runtime.h>

// ---------------------------------------------------------------------------
// GraphConvLSTM on GB300 — Round 4: fused persistent kernel.
// grid = 128 blocks x 256 threads = 4 groups x 64 threads (1 batch each).
// Microtile 6 rows x 8 cols (two 4-col slabs at jt*4 and jt*4+64) =>
//   - W smem traffic halved vs R3
//   - conflict-free 256B W loads
//   - c and xg register-resident (255-reg budget at 1 block/SM)
// ---------------------------------------------------------------------------

#define BATCH   512
#define INDIM   256
#define HDIM    128
#define TSTEPS  100
#define NNODES  22
#define MROWS   24
#define GROUPS  4
#define GTHR    64

// -------------------- scratch (device globals, no allocs) ------------------
__device__ float g_xg[BATCH * HDIM * 4];   // packed [b][j][gate i,f,o,c]

// -------------------- normalized adjacency (baked constants) ---------------
__constant__ int c_cnt[NNODES] = {13,4,4,5,4,4,5,4,4,13,4,4,5,4,4,5,4,4,4,4,4,4};
__constant__ int c_nbr[NNODES][13] = {
    {1,2,3,4,5,6,7,8,9,10,11,12,15},
    {0,4,7,10, 0,0,0,0,0,0,0,0,0},
    {0,5,8,11, 0,0,0,0,0,0,0,0,0},
    {0,6,9,12,15, 0,0,0,0,0,0,0,0},
    {0,1,7,10, 0,0,0,0,0,0,0,0,0},
    {0,2,8,11, 0,0,0,0,0,0,0,0,0},
    {0,3,9,12,15, 0,0,0,0,0,0,0,0},
    {0,1,4,10, 0,0,0,0,0,0,0,0,0},
    {0,2,5,11, 0,0,0,0,0,0,0,0,0},
    {0,3,6,12,15,13,14,16,17,18,19,20,21},
    {0,1,4,7, 0,0,0,0,0,0,0,0,0},
    {0,2,5,8, 0,0,0,0,0,0,0,0,0},
    {0,3,6,9,15, 0,0,0,0,0,0,0,0},
    {9,16,18,20, 0,0,0,0,0,0,0,0,0},
    {9,17,19,21, 0,0,0,0,0,0,0,0,0},
    {0,3,6,9,12, 0,0,0,0,0,0,0,0},
    {9,13,18,20, 0,0,0,0,0,0,0,0,0},
    {9,14,19,21, 0,0,0,0,0,0,0,0,0},
    {9,13,16,20, 0,0,0,0,0,0,0,0,0},
    {9,14,17,21, 0,0,0,0,0,0,0,0,0},
    {9,13,16,18, 0,0,0,0,0,0,0,0,0},
    {9,14,17,19, 0,0,0,0,0,0,0,0,0}
};
__constant__ float c_dinv[NNODES] = {
    0.2773500979f, 0.5f, 0.5f, 0.4472135955f, 0.5f, 0.5f, 0.4472135955f, 0.5f, 0.5f,
    0.2773500979f, 0.5f, 0.5f, 0.4472135955f, 0.5f, 0.5f, 0.4472135955f,
    0.5f, 0.5f, 0.5f, 0.5f, 0.5f, 0.5f
};

// -------------------- packed f32x2 helpers ----------------------------------
__device__ __forceinline__ unsigned long long bcast2(float x) {
    unsigned long long r;
    asm("mov.b64 %0, {%1, %1};" : "=l"(r) : "f"(x));
    return r;
}
__device__ __forceinline__ void fma2(unsigned long long& d,
                                     unsigned long long a, unsigned long long b) {
    asm("fma.rn.f32x2 %0, %1, %2, %0;" : "+l"(d) : "l"(a), "l"(b));
}
__device__ __forceinline__ float2 unpk2(unsigned long long v) {
    float2 f;
    asm("mov.b64 {%0, %1}, %2;" : "=f"(f.x), "=f"(f.y) : "l"(v));
    return f;
}

// -------------------- math helpers (saturation-safe) ------------------------
__device__ __forceinline__ float fsig(float x) {
    return __fdividef(1.0f, 1.0f + __expf(-x));
}
__device__ __forceinline__ float ftanh_(float x) {
    return 1.0f - __fdividef(2.0f, __expf(2.0f * x) + 1.0f);
}

// -------------------- gate projection: packed xg ----------------------------
__global__ __launch_bounds__(128) void gate_kernel(
    const float* __restrict__ x,
    const float* __restrict__ wi, const float* __restrict__ bi,
    const float* __restrict__ wf, const float* __restrict__ bf,
    const float* __restrict__ wo, const float* __restrict__ bo,
    const float* __restrict__ wc, const float* __restrict__ bc)
{
    __shared__ float xs[16 * INDIM];
    __shared__ float ws[32 * 129];

    int tid  = threadIdx.x;
    int gate = blockIdx.y;
    const float* w    = (gate == 0) ? wi : (gate == 1) ? wf : (gate == 2) ? wo : wc;
    const float* bias = (gate == 0) ? bi : (gate == 1) ? bf : (gate == 2) ? bo : bc;
    int b0 = blockIdx.x * 16;

    for (int i = tid; i < 16 * INDIM; i += 128) xs[i] = x[b0 * INDIM + i];

    float acc[16];
#pragma unroll
    for (int bb = 0; bb < 16; bb++) acc[bb] = 0.f;

    for (int k0 = 0; k0 < INDIM; k0 += 32) {
        __syncthreads();
        for (int i = tid; i < 128 * 32; i += 128) {
            int j = i >> 5, k = i & 31;
            ws[k * 129 + j] = w[j * INDIM + k0 + k];
        }
        __syncthreads();
#pragma unroll 8
        for (int k = 0; k < 32; k++) {
            float wv = ws[k * 129 + tid];
#pragma unroll
            for (int bb = 0; bb < 16; bb++)
                acc[bb] += xs[bb * INDIM + k0 + k] * wv;
        }
    }
    float bv = bias[tid];
#pragma unroll
    for (int bb = 0; bb < 16; bb++)
        g_xg[((b0 + bb) * HDIM + tid) * 4 + gate] = acc[bb] + bv;
}

// -------------------- fused recurrence ---------------------------------------
// dyn smem: ws[128*128] | per group: ms[24*128], hs[24*128]   (160 KB)
__global__ __launch_bounds__(256, 1) void fused_kernel(
    const float* __restrict__ gw,
    const float* __restrict__ gb,
    float* __restrict__ out)
{
    extern __shared__ float dyn[];
    float* ws = dyn;                                   // 16384 floats (64 KB)

    const int tid  = threadIdx.x;
    const int g    = tid >> 6;          // group 0..3
    const int ltid = tid & 63;
    const int b    = blockIdx.x * GROUPS + g;

    float* ms = dyn + HDIM * HDIM + g * (2 * MROWS * HDIM);
    float* hs = ms + MROWS * HDIM;

    const int jt  = ltid & 15;          // 16 col groups
    const int rg  = ltid >> 4;          // 4 row groups x 6 rows
    const int j0a = jt * 4;             // first 4-col slab
    const int j0b = jt * 4 + 64;        // second 4-col slab

    // ---- block-cooperative init: W once, zero ms+hs ----
    {
        const float4* g4 = reinterpret_cast<const float4*>(gw);
        float4*       w4 = reinterpret_cast<float4*>(ws);
        for (int i = tid; i < HDIM * HDIM / 4; i += 256) w4[i] = g4[i];

        float4 z = make_float4(0.f, 0.f, 0.f, 0.f);
        float4* z4 = reinterpret_cast<float4*>(dyn + HDIM * HDIM);
        for (int i = tid; i < GROUPS * 2 * MROWS * HDIM / 4; i += 256) z4[i] = z;
    }

    // ---- persistent registers: gate inputs (bias folded), gcn bias, cell ----
    float xi[8], xf[8], xo[8], xc[8], gbr[8];
    const float4* xg4 = reinterpret_cast<const float4*>(g_xg);
#pragma unroll
    for (int q = 0; q < 8; q++) {
        int j = (q < 4) ? (j0a + q) : (j0b + q - 4);
        float4 v = xg4[b * HDIM + j];
        float gbv = gb[j];
        gbr[q] = gbv;
        xi[q] = v.x; xf[q] = v.y; xo[q] = v.z; xc[q] = v.w;
    }

    float c[6][8];
#pragma unroll
    for (int i = 0; i < 6; i++)
#pragma unroll
        for (int q = 0; q < 8; q++) c[i][q] = 0.f;

    __syncthreads();    // init visible; groups free-run below

    const float4* msv = reinterpret_cast<const float4*>(ms);
    const int bar = g + 1;

    for (int t = 0; t < TSTEPS; t++) {
        // ---- msg = A_norm @ h (smem->smem): 22 rows x 32 float4 = 704 tasks ----
#pragma unroll
        for (int p = 0; p < 11; p++) {
            int task = p * 64 + ltid;
            int row  = task >> 5;
            int cq   = (task & 31) << 2;
            int   cnt = c_cnt[row];
            float dm  = c_dinv[row];
            float4 a = make_float4(0.f, 0.f, 0.f, 0.f);
            for (int q = 0; q < cnt; q++) {
                int   n  = c_nbr[row][q];
                float cf = dm * c_dinv[n];
                float4 hv = *reinterpret_cast<const float4*>(hs + n * HDIM + cq);
                a.x += cf * hv.x; a.y += cf * hv.y;
                a.z += cf * hv.z; a.w += cf * hv.w;
            }
            *reinterpret_cast<float4*>(ms + row * HDIM + cq) = a;
        }
        asm volatile("bar.sync %0, 64;" :: "r"(bar) : "memory");

        // ---- GEMM: acc(6x8) = msg(6x128) @ W(128x8) via FFMA2 ----
        unsigned long long acc[6][4];
#pragma unroll
        for (int i = 0; i < 6; i++)
#pragma unroll
            for (int q = 0; q < 4; q++) acc[i][q] = 0ull;

#pragma unroll 2
        for (int kq = 0; kq < 32; kq++) {
            float4 m[6];
#pragma unroll
            for (int i = 0; i < 6; i++) m[i] = msv[(rg * 6 + i) * 32 + kq];
#pragma unroll
            for (int kk = 0; kk < 4; kk++) {
                const float* wrow = ws + ((kq * 4 + kk) << 7);
                ulonglong2 wa = *reinterpret_cast<const ulonglong2*>(wrow + j0a);
                ulonglong2 wb = *reinterpret_cast<const ulonglong2*>(wrow + j0b);
#pragma unroll
                for (int i = 0; i < 6; i++) {
                    float mv = (kk == 0) ? m[i].x : (kk == 1) ? m[i].y
                             : (kk == 2) ? m[i].z : m[i].w;
                    unsigned long long p = bcast2(mv);
                    fma2(acc[i][0], p, wa.x);
                    fma2(acc[i][1], p, wa.y);
                    fma2(acc[i][2], p, wb.x);
                    fma2(acc[i][3], p, wb.y);
                }
            }
        }

        // ---- LSTM epilogue ----
#pragma unroll
        for (int i = 0; i < 6; i++) {
            int r = rg * 6 + i;
            if (r < NNODES) {
                float2 t01 = unpk2(acc[i][0]);
                float2 t23 = unpk2(acc[i][1]);
                float2 t45 = unpk2(acc[i][2]);
                float2 t67 = unpk2(acc[i][3]);
                float gv[8] = {t01.x, t01.y, t23.x, t23.y,
                               t45.x, t45.y, t67.x, t67.y};
                float hv[8];
#pragma unroll
                for (int q = 0; q < 8; q++) {
                    float gg = gv[q] + gbr[q];
                    float it = fsig(xi[q] + gg);
                    float ft = fsig(xf[q] + gg);
                    float ot = fsig(xo[q] + gg);
                    float ct = ftanh_(xc[q] + gg);
                    float cn = ft * c[i][q] + it * ct;
                    c[i][q] = cn;
                    hv[q] = ot * ftanh_(cn);
                }
                float4 ha = make_float4(hv[0], hv[1], hv[2], hv[3]);
                float4 hb = make_float4(hv[4], hv[5], hv[6], hv[7]);
                *reinterpret_cast<float4*>(hs + r * HDIM + j0a) = ha;
                *reinterpret_cast<float4*>(hs + r * HDIM + j0b) = hb;
                float* ob = out + (((size_t)b * TSTEPS + t) * NNODES + r) * HDIM;
                *reinterpret_cast<float4*>(ob + j0a) = ha;
                *reinterpret_cast<float4*>(ob + j0b) = hb;
            }
        }
        asm volatile("bar.sync %0, 64;" :: "r"(bar) : "memory");
    }
}

// -------------------- launch -------------------------------------------------
extern "C" void kernel_launch(void* const* d_in, const int* in_sizes, int n_in,
                              void* d_out, int out_size) {
    (void)in_sizes; (void)n_in; (void)out_size;
    const float* x     = (const float*)d_in[0];
    const float* wi_w  = (const float*)d_in[1];
    const float* wi_b  = (const float*)d_in[2];
    const float* wf_w  = (const float*)d_in[3];
    const float* wf_b  = (const float*)d_in[4];
    const float* wo_w  = (const float*)d_in[5];
    const float* wo_b  = (const float*)d_in[6];
    const float* wc_w  = (const float*)d_in[7];
    const float* wc_b  = (const float*)d_in[8];
    const float* gcn_w = (const float*)d_in[9];
    const float* gcn_b = (const float*)d_in[10];
    float* out = (float*)d_out;

    const int smem_bytes =
        (HDIM * HDIM + GROUPS * 2 * MROWS * HDIM) * sizeof(float);   // 160 KB
    cudaFuncSetAttribute(fused_kernel,
                         cudaFuncAttributeMaxDynamicSharedMemorySize, smem_bytes);

    gate_kernel<<<dim3(BATCH / 16, 4), 128>>>(x, wi_w, wi_b, wf_w, wf_b,
                                              wo_w, wo_b, wc_w, wc_b);
    fused_kernel<<<BATCH / GROUPS, 256, smem_bytes>>>(gcn_w, gcn_b, out);
}

// round 5
// speedup vs baseline: 2.7016x; 1.7070x over previous
#include <cuda_runtime.h>
#include <cuda_bf16.h>
#include <cstdint>

// ---------------------------------------------------------------------------
// GraphConvLSTM on GB300 — Round 5: tensor-core GEMM (bf16 hi/lo split, 3 mma)
// grid 128 x 512 thr = 4 groups x 4 warps; 1 batch per group, persistent.
// W^T bf16 planes in smem (block-shared); msg bf16 planes per group;
// epilogue fp32 exactly as before; coalesced out copy via smem.
// ---------------------------------------------------------------------------

#define BATCH   512
#define INDIM   256
#define HDIM    128
#define TSTEPS  100
#define NNODES  22
#define GROUPS  4

// smem word layout (4B words)
#define WT_WORDS   (128 * 68)            // one W^T bf16 plane (padded stride 68)
#define MS_WORDS   (32 * 68)             // one msg bf16 plane (32 rows)
#define HS_WORDS   (24 * 132)            // h fp32, stride 132
#define XG_WORDS   (128 * 4)             // packed gates per column
#define GRP_WORDS  (2 * MS_WORDS + HS_WORDS + XG_WORDS)   // 8032
#define TOT_WORDS  (2 * WT_WORDS + GROUPS * GRP_WORDS)    // 49536

// -------------------- scratch (device globals, no allocs) ------------------
__device__ float g_xg[BATCH * HDIM * 4];   // packed [b][j][gate i,f,o,c]

// -------------------- normalized adjacency (baked constants) ---------------
__constant__ int c_cnt[NNODES] = {13,4,4,5,4,4,5,4,4,13,4,4,5,4,4,5,4,4,4,4,4,4};
__constant__ int c_nbr[NNODES][13] = {
    {1,2,3,4,5,6,7,8,9,10,11,12,15},
    {0,4,7,10, 0,0,0,0,0,0,0,0,0},
    {0,5,8,11, 0,0,0,0,0,0,0,0,0},
    {0,6,9,12,15, 0,0,0,0,0,0,0,0},
    {0,1,7,10, 0,0,0,0,0,0,0,0,0},
    {0,2,8,11, 0,0,0,0,0,0,0,0,0},
    {0,3,9,12,15, 0,0,0,0,0,0,0,0},
    {0,1,4,10, 0,0,0,0,0,0,0,0,0},
    {0,2,5,11, 0,0,0,0,0,0,0,0,0},
    {0,3,6,12,15,13,14,16,17,18,19,20,21},
    {0,1,4,7, 0,0,0,0,0,0,0,0,0},
    {0,2,5,8, 0,0,0,0,0,0,0,0,0},
    {0,3,6,9,15, 0,0,0,0,0,0,0,0},
    {9,16,18,20, 0,0,0,0,0,0,0,0,0},
    {9,17,19,21, 0,0,0,0,0,0,0,0,0},
    {0,3,6,9,12, 0,0,0,0,0,0,0,0},
    {9,13,18,20, 0,0,0,0,0,0,0,0,0},
    {9,14,19,21, 0,0,0,0,0,0,0,0,0},
    {9,13,16,20, 0,0,0,0,0,0,0,0,0},
    {9,14,17,21, 0,0,0,0,0,0,0,0,0},
    {9,13,16,18, 0,0,0,0,0,0,0,0,0},
    {9,14,17,19, 0,0,0,0,0,0,0,0,0}
};
__constant__ float c_dinv[NNODES] = {
    0.2773500979f, 0.5f, 0.5f, 0.4472135955f, 0.5f, 0.5f, 0.4472135955f, 0.5f, 0.5f,
    0.2773500979f, 0.5f, 0.5f, 0.4472135955f, 0.5f, 0.5f, 0.4472135955f,
    0.5f, 0.5f, 0.5f, 0.5f, 0.5f, 0.5f
};

// -------------------- helpers ------------------------------------------------
__device__ __forceinline__ uint32_t pack_bf16(float a, float b) {
    __nv_bfloat162 v = __floats2bfloat162_rn(a, b);   // .x = a (low), .y = b
    return *reinterpret_cast<uint32_t*>(&v);
}
__device__ __forceinline__ void split_bf16(float f, float& hi, float& lo) {
    __nv_bfloat16 h = __float2bfloat16(f);
    hi = __bfloat162float(h);
    lo = f - hi;
}
__device__ __forceinline__ float fsig(float x) {
    return __fdividef(1.0f, 1.0f + __expf(-x));
}
__device__ __forceinline__ float ftanh_(float x) {
    return 1.0f - __fdividef(2.0f, __expf(2.0f * x) + 1.0f);
}

#define MMA_BF16(D, A0, A1, A2, A3, B0, B1)                                    \
    asm volatile(                                                              \
        "mma.sync.aligned.m16n8k16.row.col.f32.bf16.bf16.f32 "                 \
        "{%0,%1,%2,%3}, {%4,%5,%6,%7}, {%8,%9}, {%0,%1,%2,%3};"                \
        : "+f"((D)[0]), "+f"((D)[1]), "+f"((D)[2]), "+f"((D)[3])               \
        : "r"(A0), "r"(A1), "r"(A2), "r"(A3), "r"(B0), "r"(B1))

// -------------------- gate projection: packed xg ----------------------------
__global__ __launch_bounds__(128) void gate_kernel(
    const float* __restrict__ x,
    const float* __restrict__ wi, const float* __restrict__ bi,
    const float* __restrict__ wf, const float* __restrict__ bf,
    const float* __restrict__ wo, const float* __restrict__ bo,
    const float* __restrict__ wc, const float* __restrict__ bc)
{
    __shared__ float xs[16 * INDIM];
    __shared__ float ws[32 * 129];

    int tid  = threadIdx.x;
    int gate = blockIdx.y;
    const float* w    = (gate == 0) ? wi : (gate == 1) ? wf : (gate == 2) ? wo : wc;
    const float* bias = (gate == 0) ? bi : (gate == 1) ? bf : (gate == 2) ? bo : bc;
    int b0 = blockIdx.x * 16;

    for (int i = tid; i < 16 * INDIM; i += 128) xs[i] = x[b0 * INDIM + i];

    float acc[16];
#pragma unroll
    for (int bb = 0; bb < 16; bb++) acc[bb] = 0.f;

    for (int k0 = 0; k0 < INDIM; k0 += 32) {
        __syncthreads();
        for (int i = tid; i < 128 * 32; i += 128) {
            int j = i >> 5, k = i & 31;
            ws[k * 129 + j] = w[j * INDIM + k0 + k];
        }
        __syncthreads();
#pragma unroll 8
        for (int k = 0; k < 32; k++) {
            float wv = ws[k * 129 + tid];
#pragma unroll
            for (int bb = 0; bb < 16; bb++)
                acc[bb] += xs[bb * INDIM + k0 + k] * wv;
        }
    }
    float bv = bias[tid];
#pragma unroll
    for (int bb = 0; bb < 16; bb++)
        g_xg[((b0 + bb) * HDIM + tid) * 4 + gate] = acc[bb] + bv;
}

// -------------------- fused recurrence (tensor-core GEMM) --------------------
__global__ __launch_bounds__(512, 1) void fused_kernel(
    const float* __restrict__ gw,
    const float* __restrict__ gb,
    float* __restrict__ out)
{
    extern __shared__ uint32_t smw[];     // word-addressed dynamic smem
    uint32_t* wth = smw;                  // W^T hi plane [n][kword], stride 68
    uint32_t* wtl = smw + WT_WORDS;       // W^T lo plane

    const int tid  = threadIdx.x;
    const int g    = tid >> 7;            // group 0..3
    const int ltid = tid & 127;
    const int lane = tid & 31;
    const int wig  = ltid >> 5;           // warp in group 0..3
    const int b    = blockIdx.x * GROUPS + g;

    uint32_t* grp = smw + 2 * WT_WORDS + g * GRP_WORDS;
    uint32_t* msh = grp;                              // msg hi plane
    uint32_t* msl = grp + MS_WORDS;                   // msg lo plane
    float*    hs  = reinterpret_cast<float*>(grp + 2 * MS_WORDS);   // h fp32
    float*    xgs = hs + HS_WORDS;                    // packed gates [j][4]

    // ---------- init phase 1: W^T split planes + zero group regions ----------
    for (int idx = tid; idx < 128 * 64; idx += 512) {
        int n  = idx >> 6;
        int k2 = idx & 63;
        float w0 = gw[(2 * k2) * HDIM + n];
        float w1 = gw[(2 * k2 + 1) * HDIM + n];
        float h0, l0, h1, l1;
        split_bf16(w0, h0, l0);
        split_bf16(w1, h1, l1);
        wth[n * 68 + k2] = pack_bf16(h0, h1);
        wtl[n * 68 + k2] = pack_bf16(l0, l1);
    }
    for (int i = tid; i < GROUPS * GRP_WORDS; i += 512)
        smw[2 * WT_WORDS + i] = 0u;
    __syncthreads();

    // ---------- init phase 2: per-group packed gates (gcn bias folded) -------
    {
        const float4* xg4 = reinterpret_cast<const float4*>(g_xg);
        float4 v  = xg4[b * HDIM + ltid];
        float gbv = gb[ltid];
        xgs[ltid * 4 + 0] = v.x + gbv;
        xgs[ltid * 4 + 1] = v.y + gbv;
        xgs[ltid * 4 + 2] = v.z + gbv;
        xgs[ltid * 4 + 3] = v.w + gbv;
    }
    __syncthreads();

    // ---------- persistent per-thread state ----------
    const int lq  = lane >> 2;            // 0..7
    const int kw  = lane & 3;             // 0..3
    const int wof = wig * 32;             // warp's N offset

    float cst[3][8];                      // cell state: 3 row-slots x 8 cols
#pragma unroll
    for (int i = 0; i < 3; i++)
#pragma unroll
        for (int q = 0; q < 8; q++) cst[i][q] = 0.f;

    const int bar = g + 1;

    for (int t = 0; t < TSTEPS; t++) {
        // ---- msg phase: msg = A @ h  ->  bf16 hi/lo planes ----
#pragma unroll
        for (int p = 0; p < 6; p++) {
            int task = p * 128 + ltid;
            if (task < NNODES * 32) {
                int row = task >> 5;
                int cq  = (task & 31) << 2;
                int   cnt = c_cnt[row];
                float dm  = c_dinv[row];
                float4 a = make_float4(0.f, 0.f, 0.f, 0.f);
                for (int q = 0; q < cnt; q++) {
                    int   n  = c_nbr[row][q];
                    float cf = dm * c_dinv[n];
                    float4 hv = *reinterpret_cast<const float4*>(hs + n * 132 + cq);
                    a.x += cf * hv.x; a.y += cf * hv.y;
                    a.z += cf * hv.z; a.w += cf * hv.w;
                }
                float hx, lx, hy, ly, hz, lz, hw, lw;
                split_bf16(a.x, hx, lx); split_bf16(a.y, hy, ly);
                split_bf16(a.z, hz, lz); split_bf16(a.w, hw, lw);
                int wb = row * 68 + (cq >> 1);
                msh[wb]     = pack_bf16(hx, hy);
                msh[wb + 1] = pack_bf16(hz, hw);
                msl[wb]     = pack_bf16(lx, ly);
                msl[wb + 1] = pack_bf16(lz, lw);
            }
        }
        asm volatile("bar.sync %0, 128;" :: "r"(bar) : "memory");

        // ---- mma phase: acc(2 mtiles x 4 ntiles) over K=128 ----
        float acc[2][4][4];
#pragma unroll
        for (int mt = 0; mt < 2; mt++)
#pragma unroll
            for (int nt = 0; nt < 4; nt++)
#pragma unroll
                for (int q = 0; q < 4; q++) acc[mt][nt][q] = 0.f;

#pragma unroll 2
        for (int kt = 0; kt < 8; kt++) {
            int ak = kt * 8 + kw;
            // A fragments (hi, lo) for both m-tiles
            uint32_t ah[8], al[8];
#pragma unroll
            for (int mt = 0; mt < 2; mt++) {
                int rb = lq + mt * 16;
                ah[mt * 4 + 0] = msh[rb * 68 + ak];
                ah[mt * 4 + 1] = msh[(rb + 8) * 68 + ak];
                ah[mt * 4 + 2] = msh[rb * 68 + ak + 4];
                ah[mt * 4 + 3] = msh[(rb + 8) * 68 + ak + 4];
                al[mt * 4 + 0] = msl[rb * 68 + ak];
                al[mt * 4 + 1] = msl[(rb + 8) * 68 + ak];
                al[mt * 4 + 2] = msl[rb * 68 + ak + 4];
                al[mt * 4 + 3] = msl[(rb + 8) * 68 + ak + 4];
            }
#pragma unroll
            for (int nt = 0; nt < 4; nt++) {
                int nb = (wof + nt * 8 + lq) * 68 + ak;
                uint32_t bh0 = wth[nb], bh1 = wth[nb + 4];
                uint32_t bl0 = wtl[nb], bl1 = wtl[nb + 4];
#pragma unroll
                for (int mt = 0; mt < 2; mt++) {
                    MMA_BF16(acc[mt][nt], ah[mt*4+0], ah[mt*4+1], ah[mt*4+2], ah[mt*4+3], bh0, bh1);
                    MMA_BF16(acc[mt][nt], ah[mt*4+0], ah[mt*4+1], ah[mt*4+2], ah[mt*4+3], bl0, bl1);
                    MMA_BF16(acc[mt][nt], al[mt*4+0], al[mt*4+1], al[mt*4+2], al[mt*4+3], bh0, bh1);
                }
            }
        }

        // ---- epilogue: gates, cell update, h -> hs ----
#pragma unroll
        for (int nt = 0; nt < 4; nt++) {
            int c0 = wof + nt * 8 + (kw << 1);
            float4 xga = *reinterpret_cast<const float4*>(&xgs[c0 * 4]);
            float4 xgb = *reinterpret_cast<const float4*>(&xgs[(c0 + 1) * 4]);
#pragma unroll
            for (int s = 0; s < 3; s++) {
                int row = (s == 0) ? lq : (s == 1) ? (lq + 8) : (lq + 16);
                bool valid = (s < 2) || (row < NNODES);
                float d0 = (s == 2) ? acc[1][nt][0] : acc[0][nt][s * 2 + 0];
                float d1 = (s == 2) ? acc[1][nt][1] : acc[0][nt][s * 2 + 1];
                // element 0 (col c0)
                float it = fsig(xga.x + d0);
                float ft = fsig(xga.y + d0);
                float ot = fsig(xga.z + d0);
                float ct = ftanh_(xga.w + d0);
                float cn0 = ft * cst[s][nt * 2 + 0] + it * ct;
                cst[s][nt * 2 + 0] = cn0;
                float h0 = ot * ftanh_(cn0);
                // element 1 (col c0+1)
                it = fsig(xgb.x + d1);
                ft = fsig(xgb.y + d1);
                ot = fsig(xgb.z + d1);
                ct = ftanh_(xgb.w + d1);
                float cn1 = ft * cst[s][nt * 2 + 1] + it * ct;
                cst[s][nt * 2 + 1] = cn1;
                float h1 = ot * ftanh_(cn1);
                if (valid) {
                    float2 hv = make_float2(h0, h1);
                    *reinterpret_cast<float2*>(hs + row * 132 + c0) = hv;
                }
            }
        }
        asm volatile("bar.sync %0, 128;" :: "r"(bar) : "memory");

        // ---- copy phase: coalesced h -> out[t] ----
        {
            float* ob = out + ((size_t)b * TSTEPS + t) * (NNODES * HDIM);
#pragma unroll
            for (int p = 0; p < 6; p++) {
                int task = p * 128 + ltid;
                if (task < NNODES * 32) {
                    int row = task >> 5;
                    int cq  = (task & 31) << 2;
                    float4 v = *reinterpret_cast<const float4*>(hs + row * 132 + cq);
                    *reinterpret_cast<float4*>(ob + row * HDIM + cq) = v;
                }
            }
        }
        // no barrier needed: msg (next iter) reads hs only; ms was consumed
        // by all group warps before the post-epilogue barrier above.
    }
}

// -------------------- launch -------------------------------------------------
extern "C" void kernel_launch(void* const* d_in, const int* in_sizes, int n_in,
                              void* d_out, int out_size) {
    (void)in_sizes; (void)n_in; (void)out_size;
    const float* x     = (const float*)d_in[0];
    const float* wi_w  = (const float*)d_in[1];
    const float* wi_b  = (const float*)d_in[2];
    const float* wf_w  = (const float*)d_in[3];
    const float* wf_b  = (const float*)d_in[4];
    const float* wo_w  = (const float*)d_in[5];
    const float* wo_b  = (const float*)d_in[6];
    const float* wc_w  = (const float*)d_in[7];
    const float* wc_b  = (const float*)d_in[8];
    const float* gcn_w = (const float*)d_in[9];
    const float* gcn_b = (const float*)d_in[10];
    float* out = (float*)d_out;

    const int smem_bytes = TOT_WORDS * 4;   // 198144 B
    cudaFuncSetAttribute(fused_kernel,
                         cudaFuncAttributeMaxDynamicSharedMemorySize, smem_bytes);

    gate_kernel<<<dim3(BATCH / 16, 4), 128>>>(x, wi_w, wi_b, wf_w, wf_b,
                                              wo_w, wo_b, wc_w, wc_b);
    fused_kernel<<<BATCH / GROUPS, 512, smem_bytes>>>(gcn_w, gcn_b, out);
}

// round 6
// speedup vs baseline: 2.9835x; 1.1044x over previous
#include <cuda_runtime.h>
#include <cuda_bf16.h>
#include <cstdint>

// ---------------------------------------------------------------------------
// GraphConvLSTM on GB300 — Round 6: R5 + MUFU.TANH epilogue (5 MUFU/elem).
// sigmoid(x) = 0.5 + 0.5*tanh(x/2)  (gate inputs pre-halved at init)
// tensor-core GEMM (bf16 hi/lo split, 3 mma) unchanged from R5.
// ---------------------------------------------------------------------------

#define BATCH   512
#define INDIM   256
#define HDIM    128
#define TSTEPS  100
#define NNODES  22
#define GROUPS  4

// smem word layout (4B words)
#define WT_WORDS   (128 * 68)            // one W^T bf16 plane (padded stride 68)
#define MS_WORDS   (32 * 68)             // one msg bf16 plane (32 rows)
#define HS_WORDS   (24 * 132)            // h fp32, stride 132
#define XG_WORDS   (128 * 4)             // packed gates per column
#define GRP_WORDS  (2 * MS_WORDS + HS_WORDS + XG_WORDS)   // 8032
#define TOT_WORDS  (2 * WT_WORDS + GROUPS * GRP_WORDS)    // 49536

// -------------------- scratch (device globals, no allocs) ------------------
__device__ float g_xg[BATCH * HDIM * 4];   // packed [b][j][gate i,f,o,c]

// -------------------- normalized adjacency (baked constants) ---------------
__constant__ int c_cnt[NNODES] = {13,4,4,5,4,4,5,4,4,13,4,4,5,4,4,5,4,4,4,4,4,4};
__constant__ int c_nbr[NNODES][13] = {
    {1,2,3,4,5,6,7,8,9,10,11,12,15},
    {0,4,7,10, 0,0,0,0,0,0,0,0,0},
    {0,5,8,11, 0,0,0,0,0,0,0,0,0},
    {0,6,9,12,15, 0,0,0,0,0,0,0,0},
    {0,1,7,10, 0,0,0,0,0,0,0,0,0},
    {0,2,8,11, 0,0,0,0,0,0,0,0,0},
    {0,3,9,12,15, 0,0,0,0,0,0,0,0},
    {0,1,4,10, 0,0,0,0,0,0,0,0,0},
    {0,2,5,11, 0,0,0,0,0,0,0,0,0},
    {0,3,6,12,15,13,14,16,17,18,19,20,21},
    {0,1,4,7, 0,0,0,0,0,0,0,0,0},
    {0,2,5,8, 0,0,0,0,0,0,0,0,0},
    {0,3,6,9,15, 0,0,0,0,0,0,0,0},
    {9,16,18,20, 0,0,0,0,0,0,0,0,0},
    {9,17,19,21, 0,0,0,0,0,0,0,0,0},
    {0,3,6,9,12, 0,0,0,0,0,0,0,0},
    {9,13,18,20, 0,0,0,0,0,0,0,0,0},
    {9,14,19,21, 0,0,0,0,0,0,0,0,0},
    {9,13,16,20, 0,0,0,0,0,0,0,0,0},
    {9,14,17,21, 0,0,0,0,0,0,0,0,0},
    {9,13,16,18, 0,0,0,0,0,0,0,0,0},
    {9,14,17,19, 0,0,0,0,0,0,0,0,0}
};
__constant__ float c_dinv[NNODES] = {
    0.2773500979f, 0.5f, 0.5f, 0.4472135955f, 0.5f, 0.5f, 0.4472135955f, 0.5f, 0.5f,
    0.2773500979f, 0.5f, 0.5f, 0.4472135955f, 0.5f, 0.5f, 0.4472135955f,
    0.5f, 0.5f, 0.5f, 0.5f, 0.5f, 0.5f
};

// -------------------- helpers ------------------------------------------------
__device__ __forceinline__ uint32_t pack_bf16(float a, float b) {
    __nv_bfloat162 v = __floats2bfloat162_rn(a, b);
    return *reinterpret_cast<uint32_t*>(&v);
}
__device__ __forceinline__ void split_bf16(float f, float& hi, float& lo) {
    __nv_bfloat16 h = __float2bfloat16(f);
    hi = __bfloat162float(h);
    lo = f - hi;
}
__device__ __forceinline__ float tanha(float x) {
    float r;
    asm("tanh.approx.f32 %0, %1;" : "=f"(r) : "f"(x));
    return r;
}
// sigmoid(2a) = 0.5 + 0.5*tanh(a); callers pass pre-halved argument a.
__device__ __forceinline__ float sig_h(float a) {
    return fmaf(0.5f, tanha(a), 0.5f);
}

#define MMA_BF16(D, A0, A1, A2, A3, B0, B1)                                    \
    asm volatile(                                                              \
        "mma.sync.aligned.m16n8k16.row.col.f32.bf16.bf16.f32 "                 \
        "{%0,%1,%2,%3}, {%4,%5,%6,%7}, {%8,%9}, {%0,%1,%2,%3};"                \
        : "+f"((D)[0]), "+f"((D)[1]), "+f"((D)[2]), "+f"((D)[3])               \
        : "r"(A0), "r"(A1), "r"(A2), "r"(A3), "r"(B0), "r"(B1))

// -------------------- gate projection: packed xg ----------------------------
__global__ __launch_bounds__(128) void gate_kernel(
    const float* __restrict__ x,
    const float* __restrict__ wi, const float* __restrict__ bi,
    const float* __restrict__ wf, const float* __restrict__ bf,
    const float* __restrict__ wo, const float* __restrict__ bo,
    const float* __restrict__ wc, const float* __restrict__ bc)
{
    __shared__ float xs[16 * INDIM];
    __shared__ float ws[32 * 129];

    int tid  = threadIdx.x;
    int gate = blockIdx.y;
    const float* w    = (gate == 0) ? wi : (gate == 1) ? wf : (gate == 2) ? wo : wc;
    const float* bias = (gate == 0) ? bi : (gate == 1) ? bf : (gate == 2) ? bo : bc;
    int b0 = blockIdx.x * 16;

    for (int i = tid; i < 16 * INDIM; i += 128) xs[i] = x[b0 * INDIM + i];

    float acc[16];
#pragma unroll
    for (int bb = 0; bb < 16; bb++) acc[bb] = 0.f;

    for (int k0 = 0; k0 < INDIM; k0 += 32) {
        __syncthreads();
        for (int i = tid; i < 128 * 32; i += 128) {
            int j = i >> 5, k = i & 31;
            ws[k * 129 + j] = w[j * INDIM + k0 + k];
        }
        __syncthreads();
#pragma unroll 8
        for (int k = 0; k < 32; k++) {
            float wv = ws[k * 129 + tid];
#pragma unroll
            for (int bb = 0; bb < 16; bb++)
                acc[bb] += xs[bb * INDIM + k0 + k] * wv;
        }
    }
    float bv = bias[tid];
#pragma unroll
    for (int bb = 0; bb < 16; bb++)
        g_xg[((b0 + bb) * HDIM + tid) * 4 + gate] = acc[bb] + bv;
}

// -------------------- fused recurrence (tensor-core GEMM) --------------------
__global__ __launch_bounds__(512, 1) void fused_kernel(
    const float* __restrict__ gw,
    const float* __restrict__ gb,
    float* __restrict__ out)
{
    extern __shared__ uint32_t smw[];
    uint32_t* wth = smw;                  // W^T hi plane [n][kword], stride 68
    uint32_t* wtl = smw + WT_WORDS;       // W^T lo plane

    const int tid  = threadIdx.x;
    const int g    = tid >> 7;            // group 0..3
    const int ltid = tid & 127;
    const int lane = tid & 31;
    const int wig  = ltid >> 5;           // warp in group 0..3
    const int b    = blockIdx.x * GROUPS + g;

    uint32_t* grp = smw + 2 * WT_WORDS + g * GRP_WORDS;
    uint32_t* msh = grp;                              // msg hi plane
    uint32_t* msl = grp + MS_WORDS;                   // msg lo plane
    float*    hs  = reinterpret_cast<float*>(grp + 2 * MS_WORDS);   // h fp32
    float*    xgs = hs + HS_WORDS;                    // packed gates [j][4]

    // ---------- init phase 1: W^T split planes + zero group regions ----------
    for (int idx = tid; idx < 128 * 64; idx += 512) {
        int n  = idx >> 6;
        int k2 = idx & 63;
        float w0 = gw[(2 * k2) * HDIM + n];
        float w1 = gw[(2 * k2 + 1) * HDIM + n];
        float h0, l0, h1, l1;
        split_bf16(w0, h0, l0);
        split_bf16(w1, h1, l1);
        wth[n * 68 + k2] = pack_bf16(h0, h1);
        wtl[n * 68 + k2] = pack_bf16(l0, l1);
    }
    for (int i = tid; i < GROUPS * GRP_WORDS; i += 512)
        smw[2 * WT_WORDS + i] = 0u;
    __syncthreads();

    // ---------- init phase 2: packed gates; i,f,o pre-halved for tanh-sigmoid
    {
        const float4* xg4 = reinterpret_cast<const float4*>(g_xg);
        float4 v  = xg4[b * HDIM + ltid];
        float gbv = gb[ltid];
        xgs[ltid * 4 + 0] = 0.5f * (v.x + gbv);
        xgs[ltid * 4 + 1] = 0.5f * (v.y + gbv);
        xgs[ltid * 4 + 2] = 0.5f * (v.z + gbv);
        xgs[ltid * 4 + 3] = v.w + gbv;            // c~ input stays full-scale
    }
    __syncthreads();

    // ---------- persistent per-thread state ----------
    const int lq  = lane >> 2;            // 0..7
    const int kw  = lane & 3;             // 0..3
    const int wof = wig * 32;             // warp's N offset

    float cst[3][8];
#pragma unroll
    for (int i = 0; i < 3; i++)
#pragma unroll
        for (int q = 0; q < 8; q++) cst[i][q] = 0.f;

    const int bar = g + 1;

    for (int t = 0; t < TSTEPS; t++) {
        // ---- msg phase: msg = A @ h  ->  bf16 hi/lo planes ----
#pragma unroll
        for (int p = 0; p < 6; p++) {
            int task = p * 128 + ltid;
            if (task < NNODES * 32) {
                int row = task >> 5;
                int cq  = (task & 31) << 2;
                int   cnt = c_cnt[row];
                float dm  = c_dinv[row];
                float4 a = make_float4(0.f, 0.f, 0.f, 0.f);
                for (int q = 0; q < cnt; q++) {
                    int   n  = c_nbr[row][q];
                    float cf = dm * c_dinv[n];
                    float4 hv = *reinterpret_cast<const float4*>(hs + n * 132 + cq);
                    a.x += cf * hv.x; a.y += cf * hv.y;
                    a.z += cf * hv.z; a.w += cf * hv.w;
                }
                float hx, lx, hy, ly, hz, lz, hw, lw;
                split_bf16(a.x, hx, lx); split_bf16(a.y, hy, ly);
                split_bf16(a.z, hz, lz); split_bf16(a.w, hw, lw);
                int wb = row * 68 + (cq >> 1);
                msh[wb]     = pack_bf16(hx, hy);
                msh[wb + 1] = pack_bf16(hz, hw);
                msl[wb]     = pack_bf16(lx, ly);
                msl[wb + 1] = pack_bf16(lz, lw);
            }
        }
        asm volatile("bar.sync %0, 128;" :: "r"(bar) : "memory");

        // ---- mma phase: acc(2 mtiles x 4 ntiles) over K=128 ----
        float acc[2][4][4];
#pragma unroll
        for (int mt = 0; mt < 2; mt++)
#pragma unroll
            for (int nt = 0; nt < 4; nt++)
#pragma unroll
                for (int q = 0; q < 4; q++) acc[mt][nt][q] = 0.f;

#pragma unroll 2
        for (int kt = 0; kt < 8; kt++) {
            int ak = kt * 8 + kw;
            uint32_t ah[8], al[8];
#pragma unroll
            for (int mt = 0; mt < 2; mt++) {
                int rb = lq + mt * 16;
                ah[mt * 4 + 0] = msh[rb * 68 + ak];
                ah[mt * 4 + 1] = msh[(rb + 8) * 68 + ak];
                ah[mt * 4 + 2] = msh[rb * 68 + ak + 4];
                ah[mt * 4 + 3] = msh[(rb + 8) * 68 + ak + 4];
                al[mt * 4 + 0] = msl[rb * 68 + ak];
                al[mt * 4 + 1] = msl[(rb + 8) * 68 + ak];
                al[mt * 4 + 2] = msl[rb * 68 + ak + 4];
                al[mt * 4 + 3] = msl[(rb + 8) * 68 + ak + 4];
            }
#pragma unroll
            for (int nt = 0; nt < 4; nt++) {
                int nb = (wof + nt * 8 + lq) * 68 + ak;
                uint32_t bh0 = wth[nb], bh1 = wth[nb + 4];
                uint32_t bl0 = wtl[nb], bl1 = wtl[nb + 4];
#pragma unroll
                for (int mt = 0; mt < 2; mt++) {
                    MMA_BF16(acc[mt][nt], ah[mt*4+0], ah[mt*4+1], ah[mt*4+2], ah[mt*4+3], bh0, bh1);
                    MMA_BF16(acc[mt][nt], ah[mt*4+0], ah[mt*4+1], ah[mt*4+2], ah[mt*4+3], bl0, bl1);
                    MMA_BF16(acc[mt][nt], al[mt*4+0], al[mt*4+1], al[mt*4+2], al[mt*4+3], bh0, bh1);
                }
            }
        }

        // ---- epilogue: tanh-only gates (5 MUFU/elem), cell update, h -> hs --
#pragma unroll
        for (int nt = 0; nt < 4; nt++) {
            int c0 = wof + nt * 8 + (kw << 1);
            float4 xga = *reinterpret_cast<const float4*>(&xgs[c0 * 4]);
            float4 xgb = *reinterpret_cast<const float4*>(&xgs[(c0 + 1) * 4]);
#pragma unroll
            for (int s = 0; s < 3; s++) {
                int row = (s == 0) ? lq : (s == 1) ? (lq + 8) : (lq + 16);
                bool valid = (s < 2) || (row < NNODES);
                float d0 = (s == 2) ? acc[1][nt][0] : acc[0][nt][s * 2 + 0];
                float d1 = (s == 2) ? acc[1][nt][1] : acc[0][nt][s * 2 + 1];
                float hd0 = 0.5f * d0;
                float hd1 = 0.5f * d1;
                // element 0 (col c0): xga = {xi/2, xf/2, xo/2, xc}
                float it = sig_h(xga.x + hd0);
                float ft = sig_h(xga.y + hd0);
                float ot = sig_h(xga.z + hd0);
                float ct = tanha(xga.w + d0);
                float cn0 = ft * cst[s][nt * 2 + 0] + it * ct;
                cst[s][nt * 2 + 0] = cn0;
                float h0 = ot * tanha(cn0);
                // element 1 (col c0+1)
                it = sig_h(xgb.x + hd1);
                ft = sig_h(xgb.y + hd1);
                ot = sig_h(xgb.z + hd1);
                ct = tanha(xgb.w + d1);
                float cn1 = ft * cst[s][nt * 2 + 1] + it * ct;
                cst[s][nt * 2 + 1] = cn1;
                float h1 = ot * tanha(cn1);
                if (valid) {
                    float2 hv = make_float2(h0, h1);
                    *reinterpret_cast<float2*>(hs + row * 132 + c0) = hv;
                }
            }
        }
        asm volatile("bar.sync %0, 128;" :: "r"(bar) : "memory");

        // ---- copy phase: coalesced h -> out[t] ----
        {
            float* ob = out + ((size_t)b * TSTEPS + t) * (NNODES * HDIM);
#pragma unroll
            for (int p = 0; p < 6; p++) {
                int task = p * 128 + ltid;
                if (task < NNODES * 32) {
                    int row = task >> 5;
                    int cq  = (task & 31) << 2;
                    float4 v = *reinterpret_cast<const float4*>(hs + row * 132 + cq);
                    *reinterpret_cast<float4*>(ob + row * HDIM + cq) = v;
                }
            }
        }
    }
}

// -------------------- launch -------------------------------------------------
extern "C" void kernel_launch(void* const* d_in, const int* in_sizes, int n_in,
                              void* d_out, int out_size) {
    (void)in_sizes; (void)n_in; (void)out_size;
    const float* x     = (const float*)d_in[0];
    const float* wi_w  = (const float*)d_in[1];
    const float* wi_b  = (const float*)d_in[2];
    const float* wf_w  = (const float*)d_in[3];
    const float* wf_b  = (const float*)d_in[4];
    const float* wo_w  = (const float*)d_in[5];
    const float* wo_b  = (const float*)d_in[6];
    const float* wc_w  = (const float*)d_in[7];
    const float* wc_b  = (const float*)d_in[8];
    const float* gcn_w = (const float*)d_in[9];
    const float* gcn_b = (const float*)d_in[10];
    float* out = (float*)d_out;

    const int smem_bytes = TOT_WORDS * 4;   // 198144 B
    cudaFuncSetAttribute(fused_kernel,
                         cudaFuncAttributeMaxDynamicSharedMemorySize, smem_bytes);

    gate_kernel<<<dim3(BATCH / 16, 4), 128>>>(x, wi_w, wi_b, wf_w, wf_b,
                                              wo_w, wo_b, wc_w, wc_b);
    fused_kernel<<<BATCH / GROUPS, 512, smem_bytes>>>(gcn_w, gcn_b, out);
}

// round 7
// speedup vs baseline: 3.6209x; 1.2137x over previous
#include <cuda_runtime.h>
#include <cuda_bf16.h>
#include <cstdint>

// ---------------------------------------------------------------------------
// GraphConvLSTM on GB300 — Round 7: operand-swapped tensor-core GEMM.
//   g^T = W^T @ msg^T :  A = W^T (M=128, no padding), B = msg (N=24 pad of 22)
//   -> 144 HMMA/warp/step (was 192); A fragments via ldmatrix.x4.
// bf16 hi/lo 3-mma split and MUFU.TANH epilogue as in R6.
// ---------------------------------------------------------------------------

#define BATCH   512
#define INDIM   256
#define HDIM    128
#define TSTEPS  100
#define NNODES  22
#define GROUPS  4

// smem word layout (4B words)
#define WT_WORDS   (128 * 68)            // one W^T bf16 plane [n][kword], stride 68
#define MS_WORDS   (24 * 68)             // one msg bf16 plane (24 rows)
#define HS_WORDS   (24 * 132)            // h fp32, stride 132
#define XG_WORDS   (128 * 4)             // packed gates per column
#define GRP_WORDS  (2 * MS_WORDS + HS_WORDS + XG_WORDS)   // 6944
#define TOT_WORDS  (2 * WT_WORDS + GROUPS * GRP_WORDS)    // 45184 (176.5 KB)

// -------------------- scratch (device globals, no allocs) ------------------
__device__ float g_xg[BATCH * HDIM * 4];   // packed [b][j][gate i,f,o,c]

// -------------------- normalized adjacency (baked constants) ---------------
__constant__ int c_cnt[NNODES] = {13,4,4,5,4,4,5,4,4,13,4,4,5,4,4,5,4,4,4,4,4,4};
__constant__ int c_nbr[NNODES][13] = {
    {1,2,3,4,5,6,7,8,9,10,11,12,15},
    {0,4,7,10, 0,0,0,0,0,0,0,0,0},
    {0,5,8,11, 0,0,0,0,0,0,0,0,0},
    {0,6,9,12,15, 0,0,0,0,0,0,0,0},
    {0,1,7,10, 0,0,0,0,0,0,0,0,0},
    {0,2,8,11, 0,0,0,0,0,0,0,0,0},
    {0,3,9,12,15, 0,0,0,0,0,0,0,0},
    {0,1,4,10, 0,0,0,0,0,0,0,0,0},
    {0,2,5,11, 0,0,0,0,0,0,0,0,0},
    {0,3,6,12,15,13,14,16,17,18,19,20,21},
    {0,1,4,7, 0,0,0,0,0,0,0,0,0},
    {0,2,5,8, 0,0,0,0,0,0,0,0,0},
    {0,3,6,9,15, 0,0,0,0,0,0,0,0},
    {9,16,18,20, 0,0,0,0,0,0,0,0,0},
    {9,17,19,21, 0,0,0,0,0,0,0,0,0},
    {0,3,6,9,12, 0,0,0,0,0,0,0,0},
    {9,13,18,20, 0,0,0,0,0,0,0,0,0},
    {9,14,19,21, 0,0,0,0,0,0,0,0,0},
    {9,13,16,20, 0,0,0,0,0,0,0,0,0},
    {9,14,17,21, 0,0,0,0,0,0,0,0,0},
    {9,13,16,18, 0,0,0,0,0,0,0,0,0},
    {9,14,17,19, 0,0,0,0,0,0,0,0,0}
};
__constant__ float c_dinv[NNODES] = {
    0.2773500979f, 0.5f, 0.5f, 0.4472135955f, 0.5f, 0.5f, 0.4472135955f, 0.5f, 0.5f,
    0.2773500979f, 0.5f, 0.5f, 0.4472135955f, 0.5f, 0.5f, 0.4472135955f,
    0.5f, 0.5f, 0.5f, 0.5f, 0.5f, 0.5f
};

// -------------------- helpers ------------------------------------------------
__device__ __forceinline__ uint32_t pack_bf16(float a, float b) {
    __nv_bfloat162 v = __floats2bfloat162_rn(a, b);
    return *reinterpret_cast<uint32_t*>(&v);
}
__device__ __forceinline__ void split_bf16(float f, float& hi, float& lo) {
    __nv_bfloat16 h = __float2bfloat16(f);
    hi = __bfloat162float(h);
    lo = f - hi;
}
__device__ __forceinline__ float tanha(float x) {
    float r;
    asm("tanh.approx.f32 %0, %1;" : "=f"(r) : "f"(x));
    return r;
}
__device__ __forceinline__ float sig_h(float a) {   // sigmoid(2a)
    return fmaf(0.5f, tanha(a), 0.5f);
}
__device__ __forceinline__ uint32_t smem_u32(const void* p) {
    return static_cast<uint32_t>(__cvta_generic_to_shared(p));
}

#define MMA_BF16(D, A0, A1, A2, A3, B0, B1)                                    \
    asm volatile(                                                              \
        "mma.sync.aligned.m16n8k16.row.col.f32.bf16.bf16.f32 "                 \
        "{%0,%1,%2,%3}, {%4,%5,%6,%7}, {%8,%9}, {%0,%1,%2,%3};"                \
        : "+f"((D)[0]), "+f"((D)[1]), "+f"((D)[2]), "+f"((D)[3])               \
        : "r"(A0), "r"(A1), "r"(A2), "r"(A3), "r"(B0), "r"(B1))

#define LDSM_X4(R0, R1, R2, R3, ADDR)                                          \
    asm volatile(                                                              \
        "ldmatrix.sync.aligned.m8n8.x4.shared.b16 {%0,%1,%2,%3}, [%4];"        \
        : "=r"(R0), "=r"(R1), "=r"(R2), "=r"(R3) : "r"(ADDR))

// -------------------- gate projection: packed xg ----------------------------
__global__ __launch_bounds__(128) void gate_kernel(
    const float* __restrict__ x,
    const float* __restrict__ wi, const float* __restrict__ bi,
    const float* __restrict__ wf, const float* __restrict__ bf,
    const float* __restrict__ wo, const float* __restrict__ bo,
    const float* __restrict__ wc, const float* __restrict__ bc)
{
    __shared__ float xs[16 * INDIM];
    __shared__ float ws[32 * 129];

    int tid  = threadIdx.x;
    int gate = blockIdx.y;
    const float* w    = (gate == 0) ? wi : (gate == 1) ? wf : (gate == 2) ? wo : wc;
    const float* bias = (gate == 0) ? bi : (gate == 1) ? bf : (gate == 2) ? bo : bc;
    int b0 = blockIdx.x * 16;

    for (int i = tid; i < 16 * INDIM; i += 128) xs[i] = x[b0 * INDIM + i];

    float acc[16];
#pragma unroll
    for (int bb = 0; bb < 16; bb++) acc[bb] = 0.f;

    for (int k0 = 0; k0 < INDIM; k0 += 32) {
        __syncthreads();
        for (int i = tid; i < 128 * 32; i += 128) {
            int j = i >> 5, k = i & 31;
            ws[k * 129 + j] = w[j * INDIM + k0 + k];
        }
        __syncthreads();
#pragma unroll 8
        for (int k = 0; k < 32; k++) {
            float wv = ws[k * 129 + tid];
#pragma unroll
            for (int bb = 0; bb < 16; bb++)
                acc[bb] += xs[bb * INDIM + k0 + k] * wv;
        }
    }
    float bv = bias[tid];
#pragma unroll
    for (int bb = 0; bb < 16; bb++)
        g_xg[((b0 + bb) * HDIM + tid) * 4 + gate] = acc[bb] + bv;
}

// -------------------- fused recurrence (swapped tensor-core GEMM) ------------
__global__ __launch_bounds__(512, 1) void fused_kernel(
    const float* __restrict__ gw,
    const float* __restrict__ gb,
    float* __restrict__ out)
{
    extern __shared__ uint32_t smw[];
    uint32_t* wth = smw;                  // W^T hi plane [n][kword], stride 68
    uint32_t* wtl = smw + WT_WORDS;       // W^T lo plane

    const int tid  = threadIdx.x;
    const int g    = tid >> 7;            // group 0..3
    const int ltid = tid & 127;
    const int lane = tid & 31;
    const int wig  = ltid >> 5;           // warp in group 0..3
    const int b    = blockIdx.x * GROUPS + g;

    uint32_t* grp = smw + 2 * WT_WORDS + g * GRP_WORDS;
    uint32_t* msh = grp;                              // msg hi plane [node][kword]
    uint32_t* msl = grp + MS_WORDS;                   // msg lo plane
    float*    hs  = reinterpret_cast<float*>(grp + 2 * MS_WORDS);   // h fp32 [node][j]
    float*    xgs = hs + HS_WORDS;                    // packed gates [j][4]

    // ---------- init phase 1: W^T split planes + zero group regions ----------
    for (int idx = tid; idx < 128 * 64; idx += 512) {
        int n  = idx >> 6;
        int k2 = idx & 63;
        float w0 = gw[(2 * k2) * HDIM + n];
        float w1 = gw[(2 * k2 + 1) * HDIM + n];
        float h0, l0, h1, l1;
        split_bf16(w0, h0, l0);
        split_bf16(w1, h1, l1);
        wth[n * 68 + k2] = pack_bf16(h0, h1);
        wtl[n * 68 + k2] = pack_bf16(l0, l1);
    }
    for (int i = tid; i < GROUPS * GRP_WORDS; i += 512)
        smw[2 * WT_WORDS + i] = 0u;
    __syncthreads();

    // ---------- init phase 2: packed gates; i,f,o pre-halved -----------------
    {
        const float4* xg4 = reinterpret_cast<const float4*>(g_xg);
        float4 v  = xg4[b * HDIM + ltid];
        float gbv = gb[ltid];
        xgs[ltid * 4 + 0] = 0.5f * (v.x + gbv);
        xgs[ltid * 4 + 1] = 0.5f * (v.y + gbv);
        xgs[ltid * 4 + 2] = 0.5f * (v.z + gbv);
        xgs[ltid * 4 + 3] = v.w + gbv;
    }
    __syncthreads();

    // ---------- persistent per-thread state ----------
    const int lq  = lane >> 2;            // 0..7
    const int kw  = lane & 3;             // 0..3
    const int wof = wig * 32;             // warp's slice of HDIM (M dim now)

    // ldmatrix base addresses for A = W^T fragments: [plane][mt]
    // lane -> row = wof + mt*16 + (lane&7) + ((lane>>3)&1)*8 ; +4 words if lane>=16
    uint32_t a_base[2][2];
    {
        int arow = (lane & 7) + ((lane >> 3) & 1) * 8;
        int acol = ((lane >> 4) & 1) * 4;
#pragma unroll
        for (int p = 0; p < 2; p++) {
            const uint32_t* pl = p ? wtl : wth;
#pragma unroll
            for (int mt = 0; mt < 2; mt++)
                a_base[p][mt] = smem_u32(pl + (wof + mt * 16 + arow) * 68 + acol);
        }
    }

    float cst[2][3][4];                   // cell state aligned with acc
#pragma unroll
    for (int mt = 0; mt < 2; mt++)
#pragma unroll
        for (int nt = 0; nt < 3; nt++)
#pragma unroll
            for (int q = 0; q < 4; q++) cst[mt][nt][q] = 0.f;

    const int bar = g + 1;

    for (int t = 0; t < TSTEPS; t++) {
        // ---- msg phase: msg = A_norm @ h  ->  bf16 hi/lo planes ----
#pragma unroll
        for (int p = 0; p < 6; p++) {
            int task = p * 128 + ltid;
            if (task < NNODES * 32) {
                int row = task >> 5;
                int cq  = (task & 31) << 2;
                int   cnt = c_cnt[row];
                float dm  = c_dinv[row];
                float4 a = make_float4(0.f, 0.f, 0.f, 0.f);
                for (int q = 0; q < cnt; q++) {
                    int   n  = c_nbr[row][q];
                    float cf = dm * c_dinv[n];
                    float4 hv = *reinterpret_cast<const float4*>(hs + n * 132 + cq);
                    a.x += cf * hv.x; a.y += cf * hv.y;
                    a.z += cf * hv.z; a.w += cf * hv.w;
                }
                float hx, lx, hy, ly, hz, lz, hw, lw;
                split_bf16(a.x, hx, lx); split_bf16(a.y, hy, ly);
                split_bf16(a.z, hz, lz); split_bf16(a.w, hw, lw);
                int wb = row * 68 + (cq >> 1);
                msh[wb]     = pack_bf16(hx, hy);
                msh[wb + 1] = pack_bf16(hz, hw);
                msl[wb]     = pack_bf16(lx, ly);
                msl[wb + 1] = pack_bf16(lz, lw);
            }
        }
        asm volatile("bar.sync %0, 128;" :: "r"(bar) : "memory");

        // ---- mma phase: D(2mt x 3nt) = W^T(hi/lo) @ msg(hi/lo), K=128 ----
        float acc[2][3][4];
#pragma unroll
        for (int mt = 0; mt < 2; mt++)
#pragma unroll
            for (int nt = 0; nt < 3; nt++)
#pragma unroll
                for (int q = 0; q < 4; q++) acc[mt][nt][q] = 0.f;

#pragma unroll 2
        for (int kt = 0; kt < 8; kt++) {
            const uint32_t koff = kt * 32;    // 8 words = 32 bytes per kt
            uint32_t ah[2][4], al[2][4];
#pragma unroll
            for (int mt = 0; mt < 2; mt++) {
                LDSM_X4(ah[mt][0], ah[mt][1], ah[mt][2], ah[mt][3],
                        a_base[0][mt] + koff);
                LDSM_X4(al[mt][0], al[mt][1], al[mt][2], al[mt][3],
                        a_base[1][mt] + koff);
            }
            int ak = kt * 8 + kw;
#pragma unroll
            for (int nt = 0; nt < 3; nt++) {
                int nb = (nt * 8 + lq) * 68 + ak;
                uint32_t bh0 = msh[nb], bh1 = msh[nb + 4];
                uint32_t bl0 = msl[nb], bl1 = msl[nb + 4];
#pragma unroll
                for (int mt = 0; mt < 2; mt++) {
                    MMA_BF16(acc[mt][nt], ah[mt][0], ah[mt][1], ah[mt][2], ah[mt][3], bh0, bh1);
                    MMA_BF16(acc[mt][nt], ah[mt][0], ah[mt][1], ah[mt][2], ah[mt][3], bl0, bl1);
                    MMA_BF16(acc[mt][nt], al[mt][0], al[mt][1], al[mt][2], al[mt][3], bh0, bh1);
                }
            }
        }

        // ---- epilogue: D[j][node]; thread elems (j0/j1, n0/n0+1) per (mt,nt) -
#pragma unroll
        for (int mt = 0; mt < 2; mt++) {
            int j0 = wof + mt * 16 + lq;
            int j1 = j0 + 8;
            float4 xga = *reinterpret_cast<const float4*>(&xgs[j0 * 4]);
            float4 xgb = *reinterpret_cast<const float4*>(&xgs[j1 * 4]);
#pragma unroll
            for (int nt = 0; nt < 3; nt++) {
                int n0 = nt * 8 + (kw << 1);
                bool valid = (n0 < NNODES);     // n0 even => n0+1 valid too
                // (j0, n0)
                {
                    float d = acc[mt][nt][0], hd = 0.5f * d;
                    float it = sig_h(xga.x + hd);
                    float ft = sig_h(xga.y + hd);
                    float ot = sig_h(xga.z + hd);
                    float ct = tanha(xga.w + d);
                    float cn = ft * cst[mt][nt][0] + it * ct;
                    cst[mt][nt][0] = cn;
                    if (valid) hs[n0 * 132 + j0] = ot * tanha(cn);
                }
                // (j0, n0+1)
                {
                    float d = acc[mt][nt][1], hd = 0.5f * d;
                    float it = sig_h(xga.x + hd);
                    float ft = sig_h(xga.y + hd);
                    float ot = sig_h(xga.z + hd);
                    float ct = tanha(xga.w + d);
                    float cn = ft * cst[mt][nt][1] + it * ct;
                    cst[mt][nt][1] = cn;
                    if (valid) hs[(n0 + 1) * 132 + j0] = ot * tanha(cn);
                }
                // (j1, n0)
                {
                    float d = acc[mt][nt][2], hd = 0.5f * d;
                    float it = sig_h(xgb.x + hd);
                    float ft = sig_h(xgb.y + hd);
                    float ot = sig_h(xgb.z + hd);
                    float ct = tanha(xgb.w + d);
                    float cn = ft * cst[mt][nt][2] + it * ct;
                    cst[mt][nt][2] = cn;
                    if (valid) hs[n0 * 132 + j1] = ot * tanha(cn);
                }
                // (j1, n0+1)
                {
                    float d = acc[mt][nt][3], hd = 0.5f * d;
                    float it = sig_h(xgb.x + hd);
                    float ft = sig_h(xgb.y + hd);
                    float ot = sig_h(xgb.z + hd);
                    float ct = tanha(xgb.w + d);
                    float cn = ft * cst[mt][nt][3] + it * ct;
                    cst[mt][nt][3] = cn;
                    if (valid) hs[(n0 + 1) * 132 + j1] = ot * tanha(cn);
                }
            }
        }
        asm volatile("bar.sync %0, 128;" :: "r"(bar) : "memory");

        // ---- copy phase: coalesced h -> out[t] ----
        {
            float* ob = out + ((size_t)b * TSTEPS + t) * (NNODES * HDIM);
#pragma unroll
            for (int p = 0; p < 6; p++) {
                int task = p * 128 + ltid;
                if (task < NNODES * 32) {
                    int row = task >> 5;
                    int cq  = (task & 31) << 2;
                    float4 v = *reinterpret_cast<const float4*>(hs + row * 132 + cq);
                    *reinterpret_cast<float4*>(ob + row * HDIM + cq) = v;
                }
            }
        }
    }
}

// -------------------- launch -------------------------------------------------
extern "C" void kernel_launch(void* const* d_in, const int* in_sizes, int n_in,
                              void* d_out, int out_size) {
    (void)in_sizes; (void)n_in; (void)out_size;
    const float* x     = (const float*)d_in[0];
    const float* wi_w  = (const float*)d_in[1];
    const float* wi_b  = (const float*)d_in[2];
    const float* wf_w  = (const float*)d_in[3];
    const float* wf_b  = (const float*)d_in[4];
    const float* wo_w  = (const float*)d_in[5];
    const float* wo_b  = (const float*)d_in[6];
    const float* wc_w  = (const float*)d_in[7];
    const float* wc_b  = (const float*)d_in[8];
    const float* gcn_w = (const float*)d_in[9];
    const float* gcn_b = (const float*)d_in[10];
    float* out = (float*)d_out;

    const int smem_bytes = TOT_WORDS * 4;
    cudaFuncSetAttribute(fused_kernel,
                         cudaFuncAttributeMaxDynamicSharedMemorySize, smem_bytes);

    gate_kernel<<<dim3(BATCH / 16, 4), 128>>>(x, wi_w, wi_b, wf_w, wf_b,
                                              wo_w, wo_b, wc_w, wc_b);
    fused_kernel<<<BATCH / GROUPS, 512, smem_bytes>>>(gcn_w, gcn_b, out);
}

// round 9
// speedup vs baseline: 4.5473x; 1.2558x over previous
#include <cuda_runtime.h>
#include <cuda_bf16.h>
#include <cstdint>

// ---------------------------------------------------------------------------
// GraphConvLSTM on GB300 — Round 9: associativity + warp mma (no tcgen05).
//   g = A_norm @ (h @ W):
//   1) p^T = W^T @ h^T via mma.sync bf16 hi/lo split (A=W^T M=128, B=h N=24)
//   2) p fragments -> smem; thread j reads its column, does the sparse
//      A-combine with literal coefficients (fp32), LSTM epilogue, writes
//      out directly (coalesced) and h as bf16 planes for the next step.
// 4 groups x 4 warps per 512-thread block; grid = 128.
// ---------------------------------------------------------------------------

#define BATCH   512
#define INDIM   256
#define HDIM    128
#define TSTEPS  100
#define NNODES  22
#define GROUPS  4

// smem word layout (4B words)
#define WPL_WORDS  (128 * 68)          // one W^T bf16 plane [j][kword], stride 68
#define HPL_WORDS  (24 * 68)           // one h bf16 plane [node][kword]
#define P_STRIDE   25                  // p smem row stride (odd => conflict-free)
#define P_WORDS    (128 * P_STRIDE)    // p fp32 [j][node]
#define GRP_WORDS  (2 * HPL_WORDS + P_WORDS)              // 6464
#define TOT_WORDS  (2 * WPL_WORDS + GROUPS * GRP_WORDS)   // 43264 (169 KB)

// -------------------- scratch (device globals, no allocs) ------------------
__device__ float g_xg[BATCH * HDIM * 4];   // packed [b][j][gate i,f,o,c]

// -------------------- adjacency as compile-time constants -------------------
struct AdjT { int cnt[22]; int nbr[22][13]; };
__device__ constexpr AdjT ADJ = {
    {13,4,4,5,4,4,5,4,4,13,4,4,5,4,4,5,4,4,4,4,4,4},
    {
        {1,2,3,4,5,6,7,8,9,10,11,12,15},
        {0,4,7,10, 0,0,0,0,0,0,0,0,0},
        {0,5,8,11, 0,0,0,0,0,0,0,0,0},
        {0,6,9,12,15, 0,0,0,0,0,0,0,0},
        {0,1,7,10, 0,0,0,0,0,0,0,0,0},
        {0,2,8,11, 0,0,0,0,0,0,0,0,0},
        {0,3,9,12,15, 0,0,0,0,0,0,0,0},
        {0,1,4,10, 0,0,0,0,0,0,0,0,0},
        {0,2,5,11, 0,0,0,0,0,0,0,0,0},
        {0,3,6,12,15,13,14,16,17,18,19,20,21},
        {0,1,4,7, 0,0,0,0,0,0,0,0,0},
        {0,2,5,8, 0,0,0,0,0,0,0,0,0},
        {0,3,6,9,15, 0,0,0,0,0,0,0,0},
        {9,16,18,20, 0,0,0,0,0,0,0,0,0},
        {9,17,19,21, 0,0,0,0,0,0,0,0,0},
        {0,3,6,9,12, 0,0,0,0,0,0,0,0},
        {9,13,18,20, 0,0,0,0,0,0,0,0,0},
        {9,14,19,21, 0,0,0,0,0,0,0,0,0},
        {9,13,16,20, 0,0,0,0,0,0,0,0,0},
        {9,14,17,21, 0,0,0,0,0,0,0,0,0},
        {9,13,16,18, 0,0,0,0,0,0,0,0,0},
        {9,14,17,19, 0,0,0,0,0,0,0,0,0}
    }
};
__device__ constexpr float DINV[22] = {
    0.2773500979f, 0.5f, 0.5f, 0.4472135955f, 0.5f, 0.5f, 0.4472135955f, 0.5f, 0.5f,
    0.2773500979f, 0.5f, 0.5f, 0.4472135955f, 0.5f, 0.5f, 0.4472135955f,
    0.5f, 0.5f, 0.5f, 0.5f, 0.5f, 0.5f
};

// -------------------- helpers ------------------------------------------------
__device__ __forceinline__ uint32_t pack_bf16(float a, float b) {
    __nv_bfloat162 v = __floats2bfloat162_rn(a, b);
    return *reinterpret_cast<uint32_t*>(&v);
}
__device__ __forceinline__ void split_bf16(float f, float& hi, float& lo) {
    __nv_bfloat16 h = __float2bfloat16(f);
    hi = __bfloat162float(h);
    lo = f - hi;
}
__device__ __forceinline__ float tanha(float x) {
    float r;
    asm("tanh.approx.f32 %0, %1;" : "=f"(r) : "f"(x));
    return r;
}
__device__ __forceinline__ float sig_h(float a) {   // sigmoid(2a)
    return fmaf(0.5f, tanha(a), 0.5f);
}
__device__ __forceinline__ uint32_t smem_u32(const void* p) {
    return static_cast<uint32_t>(__cvta_generic_to_shared(p));
}

#define MMA_BF16(D, A0, A1, A2, A3, B0, B1)                                    \
    asm volatile(                                                              \
        "mma.sync.aligned.m16n8k16.row.col.f32.bf16.bf16.f32 "                 \
        "{%0,%1,%2,%3}, {%4,%5,%6,%7}, {%8,%9}, {%0,%1,%2,%3};"                \
        : "+f"((D)[0]), "+f"((D)[1]), "+f"((D)[2]), "+f"((D)[3])               \
        : "r"(A0), "r"(A1), "r"(A2), "r"(A3), "r"(B0), "r"(B1))

#define LDSM_X4(R0, R1, R2, R3, ADDR)                                          \
    asm volatile(                                                              \
        "ldmatrix.sync.aligned.m8n8.x4.shared.b16 {%0,%1,%2,%3}, [%4];"        \
        : "=r"(R0), "=r"(R1), "=r"(R2), "=r"(R3) : "r"(ADDR))

// -------------------- gate projection: packed xg ----------------------------
__global__ __launch_bounds__(128) void gate_kernel(
    const float* __restrict__ x,
    const float* __restrict__ wi, const float* __restrict__ bi,
    const float* __restrict__ wf, const float* __restrict__ bf,
    const float* __restrict__ wo, const float* __restrict__ bo,
    const float* __restrict__ wc, const float* __restrict__ bc)
{
    __shared__ float xs[16 * INDIM];
    __shared__ float ws[32 * 129];

    int tid  = threadIdx.x;
    int gate = blockIdx.y;
    const float* w    = (gate == 0) ? wi : (gate == 1) ? wf : (gate == 2) ? wo : wc;
    const float* bias = (gate == 0) ? bi : (gate == 1) ? bf : (gate == 2) ? bo : bc;
    int b0 = blockIdx.x * 16;

    for (int i = tid; i < 16 * INDIM; i += 128) xs[i] = x[b0 * INDIM + i];

    float acc[16];
#pragma unroll
    for (int bb = 0; bb < 16; bb++) acc[bb] = 0.f;

    for (int k0 = 0; k0 < INDIM; k0 += 32) {
        __syncthreads();
        for (int i = tid; i < 128 * 32; i += 128) {
            int j = i >> 5, k = i & 31;
            ws[k * 129 + j] = w[j * INDIM + k0 + k];
        }
        __syncthreads();
#pragma unroll 8
        for (int k = 0; k < 32; k++) {
            float wv = ws[k * 129 + tid];
#pragma unroll
            for (int bb = 0; bb < 16; bb++)
                acc[bb] += xs[bb * INDIM + k0 + k] * wv;
        }
    }
    float bv = bias[tid];
#pragma unroll
    for (int bb = 0; bb < 16; bb++)
        g_xg[((b0 + bb) * HDIM + tid) * 4 + gate] = acc[bb] + bv;
}

// -------------------- fused recurrence ---------------------------------------
__global__ __launch_bounds__(512, 1) void fused_kernel(
    const float* __restrict__ gw,
    const float* __restrict__ gb,
    float* __restrict__ out)
{
    extern __shared__ uint32_t smw[];
    uint32_t* wth = smw;                  // W^T hi plane [j][kword], stride 68
    uint32_t* wtl = smw + WPL_WORDS;      // W^T lo plane

    const int tid  = threadIdx.x;
    const int g    = tid >> 7;            // group 0..3
    const int ltid = tid & 127;           // in combine phase: column j
    const int lane = tid & 31;
    const int wig  = ltid >> 5;           // warp in group 0..3
    const int b    = blockIdx.x * GROUPS + g;

    uint32_t* grp = smw + 2 * WPL_WORDS + g * GRP_WORDS;
    uint32_t* hhi = grp;                              // h hi plane [node][kword]
    uint32_t* hlo = grp + HPL_WORDS;                  // h lo plane
    float*    ps  = reinterpret_cast<float*>(grp + 2 * HPL_WORDS); // p [j][node]

    // ---------- init: W^T bf16 planes + zero h planes ----------
    for (int idx = tid; idx < 128 * 64; idx += 512) {
        int jr = idx >> 6;          // W^T row (output col j)
        int k2 = idx & 63;
        int k  = 2 * k2;
        float w0 = gw[k * HDIM + jr];
        float w1 = gw[(k + 1) * HDIM + jr];
        float h0, l0, h1, l1;
        split_bf16(w0, h0, l0);
        split_bf16(w1, h1, l1);
        wth[jr * 68 + k2] = pack_bf16(h0, h1);
        wtl[jr * 68 + k2] = pack_bf16(l0, l1);
    }
    for (int i = tid; i < GROUPS * GRP_WORDS; i += 512)
        smw[2 * WPL_WORDS + i] = 0u;
    __syncthreads();

    // ---------- per-thread persistent state (thread <-> j = ltid) ----------
    float xi, xf, xo, xc;
    {
        const float4 v = reinterpret_cast<const float4*>(g_xg)[b * HDIM + ltid];
        float gbv = gb[ltid];
        xi = 0.5f * (v.x + gbv);
        xf = 0.5f * (v.y + gbv);
        xo = 0.5f * (v.z + gbv);
        xc = v.w + gbv;
    }
    float c[NNODES];
#pragma unroll
    for (int m = 0; m < NNODES; m++) c[m] = 0.f;

    // ldmatrix base addresses for A = W^T fragments: [plane][mt]
    const int lq  = lane >> 2;
    const int kw  = lane & 3;
    const int wof = wig * 32;             // warp's slice of j (M dim)
    uint32_t a_base[2][2];
    {
        int arow = (lane & 7) + ((lane >> 3) & 1) * 8;
        int acol = ((lane >> 4) & 1) * 4;
#pragma unroll
        for (int p = 0; p < 2; p++) {
            const uint32_t* pl = p ? wtl : wth;
#pragma unroll
            for (int mt = 0; mt < 2; mt++)
                a_base[p][mt] = smem_u32(pl + (wof + mt * 16 + arow) * 68 + acol);
        }
    }

    const int bar = g + 1;
    __nv_bfloat16* hhi_h = reinterpret_cast<__nv_bfloat16*>(hhi);
    __nv_bfloat16* hlo_h = reinterpret_cast<__nv_bfloat16*>(hlo);

    for (int t = 0; t < TSTEPS; t++) {
        // ---- mma phase: p^T(2mt x 3nt) = W^T(hi/lo) @ h(hi/lo), K=128 ----
        float acc[2][3][4];
#pragma unroll
        for (int mt = 0; mt < 2; mt++)
#pragma unroll
            for (int nt = 0; nt < 3; nt++)
#pragma unroll
                for (int q = 0; q < 4; q++) acc[mt][nt][q] = 0.f;

#pragma unroll 2
        for (int kt = 0; kt < 8; kt++) {
            const uint32_t koff = kt * 32;
            uint32_t ah[2][4], al[2][4];
#pragma unroll
            for (int mt = 0; mt < 2; mt++) {
                LDSM_X4(ah[mt][0], ah[mt][1], ah[mt][2], ah[mt][3],
                        a_base[0][mt] + koff);
                LDSM_X4(al[mt][0], al[mt][1], al[mt][2], al[mt][3],
                        a_base[1][mt] + koff);
            }
            int ak = kt * 8 + kw;
#pragma unroll
            for (int nt = 0; nt < 3; nt++) {
                int nb = (nt * 8 + lq) * 68 + ak;
                uint32_t bh0 = hhi[nb], bh1 = hhi[nb + 4];
                uint32_t bl0 = hlo[nb], bl1 = hlo[nb + 4];
#pragma unroll
                for (int mt = 0; mt < 2; mt++) {
                    MMA_BF16(acc[mt][nt], ah[mt][0], ah[mt][1], ah[mt][2], ah[mt][3], bh0, bh1);
                    MMA_BF16(acc[mt][nt], ah[mt][0], ah[mt][1], ah[mt][2], ah[mt][3], bl0, bl1);
                    MMA_BF16(acc[mt][nt], al[mt][0], al[mt][1], al[mt][2], al[mt][3], bh0, bh1);
                }
            }
        }

        // ---- spill p fragments: ps[j][node], stride 25 ----
#pragma unroll
        for (int mt = 0; mt < 2; mt++) {
            int j0 = wof + mt * 16 + lq;
            int j1 = j0 + 8;
#pragma unroll
            for (int nt = 0; nt < 3; nt++) {
                int n0 = nt * 8 + (kw << 1);
                ps[j0 * P_STRIDE + n0]     = acc[mt][nt][0];
                ps[j0 * P_STRIDE + n0 + 1] = acc[mt][nt][1];
                ps[j1 * P_STRIDE + n0]     = acc[mt][nt][2];
                ps[j1 * P_STRIDE + n0 + 1] = acc[mt][nt][3];
            }
        }
        asm volatile("bar.sync %0, 128;" :: "r"(bar) : "memory");

        // ---- combine + epilogue: thread owns column j = ltid ----
        float p[NNODES];
#pragma unroll
        for (int n = 0; n < NNODES; n++) p[n] = ps[ltid * P_STRIDE + n];

        float* ob = out + (((size_t)b * TSTEPS + t) * NNODES) * HDIM + ltid;
#pragma unroll
        for (int m = 0; m < NNODES; m++) {
            float gacc = 0.f;
#pragma unroll
            for (int q = 0; q < 13; q++) {
                if (q < ADJ.cnt[m]) {
                    const int n = ADJ.nbr[m][q];
                    gacc = fmaf(DINV[m] * DINV[n], p[n], gacc);
                }
            }
            float hd = 0.5f * gacc;
            float it = sig_h(xi + hd);
            float ft = sig_h(xf + hd);
            float ot = sig_h(xo + hd);
            float ct = tanha(xc + gacc);
            float cn = fmaf(ft, c[m], it * ct);
            c[m] = cn;
            float hv = ot * tanha(cn);
            ob[m * HDIM] = hv;                       // coalesced across warp
            // h bf16 planes for next step's B operand: halfword (m*136 + j)
            float hh, hl;
            split_bf16(hv, hh, hl);
            hhi_h[m * 136 + ltid] = __float2bfloat16(hh);
            hlo_h[m * 136 + ltid] = __float2bfloat16(hl);
        }
        asm volatile("bar.sync %0, 128;" :: "r"(bar) : "memory");
    }
}

// -------------------- launch -------------------------------------------------
extern "C" void kernel_launch(void* const* d_in, const int* in_sizes, int n_in,
                              void* d_out, int out_size) {
    (void)in_sizes; (void)n_in; (void)out_size;
    const float* x     = (const float*)d_in[0];
    const float* wi_w  = (const float*)d_in[1];
    const float* wi_b  = (const float*)d_in[2];
    const float* wf_w  = (const float*)d_in[3];
    const float* wf_b  = (const float*)d_in[4];
    const float* wo_w  = (const float*)d_in[5];
    const float* wo_b  = (const float*)d_in[6];
    const float* wc_w  = (const float*)d_in[7];
    const float* wc_b  = (const float*)d_in[8];
    const float* gcn_w = (const float*)d_in[9];
    const float* gcn_b = (const float*)d_in[10];
    float* out = (float*)d_out;

    const int smem_bytes = TOT_WORDS * 4;   // ~169 KB
    cudaFuncSetAttribute(fused_kernel,
                         cudaFuncAttributeMaxDynamicSharedMemorySize, smem_bytes);

    gate_kernel<<<dim3(BATCH / 16, 4), 128>>>(x, wi_w, wi_b, wf_w, wf_b,
                                              wo_w, wo_b, wc_w, wc_b);
    fused_kernel<<<BATCH / GROUPS, 512, smem_bytes>>>(gcn_w, gcn_b, out);
}

// round 10
// speedup vs baseline: 4.7036x; 1.0344x over previous
#include <cuda_runtime.h>
#include <cuda_bf16.h>
#include <cstdint>

// ---------------------------------------------------------------------------
// GraphConvLSTM on GB300 — Round 10: R9 + B-ldmatrix + clique combine +
// vectorized p spill/reload + group phase stagger.
//   g = A_norm @ (h @ W):  p^T = W^T @ h^T (mma.sync bf16 hi/lo, 3 products),
//   spill p, per-column clique-factored A-combine, LSTM epilogue, direct out.
// ---------------------------------------------------------------------------

#define BATCH   512
#define INDIM   256
#define HDIM    128
#define TSTEPS  100
#define NNODES  22
#define GROUPS  4

// smem word layout (4B words)
#define WPL_WORDS  (128 * 68)          // one W^T bf16 plane [j][kword], stride 68
#define HPL_WORDS  (24 * 68)           // one h bf16 plane [node][kword]
#define P_STRIDE   28                  // p row stride: 112B, 16B-aligned, cf-free
#define P_WORDS    (128 * P_STRIDE)
#define GRP_WORDS  (2 * HPL_WORDS + P_WORDS)              // 6848
#define TOT_WORDS  (2 * WPL_WORDS + GROUPS * GRP_WORDS)   // 44800 (175 KB)

// -------------------- scratch (device globals, no allocs) ------------------
__device__ float g_xg[BATCH * HDIM * 4];   // packed [b][j][gate i,f,o,c]

// -------------------- clique-factored adjacency ------------------------------
// cliques: A=[0,2,5,8,11] B=[0,1,4,7,10] C=[0,3,6,9,12,15] D=[9,14,17,19,21]
//          E=[9,13,16,18,20];  msg[m] = dm*(sum of member-clique S - cnt*dm*p[m])
__device__ constexpr int CLQ[5][6] = {
    {0,2,5,8,11,-1}, {0,1,4,7,10,-1}, {0,3,6,9,12,15},
    {9,14,17,19,21,-1}, {9,13,16,18,20,-1}
};
__device__ constexpr int CMASK[22] = {
    7,2,1,4,2,1,4,2,1,28,2,1,4,16,8,4,16,8,16,8,16,8
};
__device__ constexpr float CCNT[22] = {
    3.f,1.f,1.f,1.f,1.f,1.f,1.f,1.f,1.f,3.f,1.f,1.f,1.f,1.f,1.f,1.f,1.f,1.f,1.f,1.f,1.f,1.f
};
__device__ constexpr float DINV[22] = {
    0.2773500979f, 0.5f, 0.5f, 0.4472135955f, 0.5f, 0.5f, 0.4472135955f, 0.5f, 0.5f,
    0.2773500979f, 0.5f, 0.5f, 0.4472135955f, 0.5f, 0.5f, 0.4472135955f,
    0.5f, 0.5f, 0.5f, 0.5f, 0.5f, 0.5f
};

// -------------------- helpers ------------------------------------------------
__device__ __forceinline__ uint32_t pack_bf16(float a, float b) {
    __nv_bfloat162 v = __floats2bfloat162_rn(a, b);
    return *reinterpret_cast<uint32_t*>(&v);
}
__device__ __forceinline__ void split_bf16(float f, float& hi, float& lo) {
    __nv_bfloat16 h = __float2bfloat16(f);
    hi = __bfloat162float(h);
    lo = f - hi;
}
__device__ __forceinline__ float tanha(float x) {
    float r;
    asm("tanh.approx.f32 %0, %1;" : "=f"(r) : "f"(x));
    return r;
}
__device__ __forceinline__ float sig_h(float a) {   // sigmoid(2a)
    return fmaf(0.5f, tanha(a), 0.5f);
}
__device__ __forceinline__ uint32_t smem_u32(const void* p) {
    return static_cast<uint32_t>(__cvta_generic_to_shared(p));
}

#define MMA_BF16(D, A0, A1, A2, A3, B0, B1)                                    \
    asm volatile(                                                              \
        "mma.sync.aligned.m16n8k16.row.col.f32.bf16.bf16.f32 "                 \
        "{%0,%1,%2,%3}, {%4,%5,%6,%7}, {%8,%9}, {%0,%1,%2,%3};"                \
        : "+f"((D)[0]), "+f"((D)[1]), "+f"((D)[2]), "+f"((D)[3])               \
        : "r"(A0), "r"(A1), "r"(A2), "r"(A3), "r"(B0), "r"(B1))

#define LDSM_X4(R0, R1, R2, R3, ADDR)                                          \
    asm volatile(                                                              \
        "ldmatrix.sync.aligned.m8n8.x4.shared.b16 {%0,%1,%2,%3}, [%4];"        \
        : "=r"(R0), "=r"(R1), "=r"(R2), "=r"(R3) : "r"(ADDR))

// -------------------- gate projection: packed xg ----------------------------
__global__ __launch_bounds__(128) void gate_kernel(
    const float* __restrict__ x,
    const float* __restrict__ wi, const float* __restrict__ bi,
    const float* __restrict__ wf, const float* __restrict__ bf,
    const float* __restrict__ wo, const float* __restrict__ bo,
    const float* __restrict__ wc, const float* __restrict__ bc)
{
    __shared__ float xs[16 * INDIM];
    __shared__ float ws[32 * 129];

    int tid  = threadIdx.x;
    int gate = blockIdx.y;
    const float* w    = (gate == 0) ? wi : (gate == 1) ? wf : (gate == 2) ? wo : wc;
    const float* bias = (gate == 0) ? bi : (gate == 1) ? bf : (gate == 2) ? bo : bc;
    int b0 = blockIdx.x * 16;

    for (int i = tid; i < 16 * INDIM; i += 128) xs[i] = x[b0 * INDIM + i];

    float acc[16];
#pragma unroll
    for (int bb = 0; bb < 16; bb++) acc[bb] = 0.f;

    for (int k0 = 0; k0 < INDIM; k0 += 32) {
        __syncthreads();
        for (int i = tid; i < 128 * 32; i += 128) {
            int j = i >> 5, k = i & 31;
            ws[k * 129 + j] = w[j * INDIM + k0 + k];
        }
        __syncthreads();
#pragma unroll 8
        for (int k = 0; k < 32; k++) {
            float wv = ws[k * 129 + tid];
#pragma unroll
            for (int bb = 0; bb < 16; bb++)
                acc[bb] += xs[bb * INDIM + k0 + k] * wv;
        }
    }
    float bv = bias[tid];
#pragma unroll
    for (int bb = 0; bb < 16; bb++)
        g_xg[((b0 + bb) * HDIM + tid) * 4 + gate] = acc[bb] + bv;
}

// -------------------- fused recurrence ---------------------------------------
__global__ __launch_bounds__(512, 1) void fused_kernel(
    const float* __restrict__ gw,
    const float* __restrict__ gb,
    float* __restrict__ out)
{
    extern __shared__ uint32_t smw[];
    uint32_t* wth = smw;                  // W^T hi plane [j][kword], stride 68
    uint32_t* wtl = smw + WPL_WORDS;      // W^T lo plane

    const int tid  = threadIdx.x;
    const int g    = tid >> 7;            // group 0..3
    const int ltid = tid & 127;           // column j in combine phase
    const int lane = tid & 31;
    const int wig  = ltid >> 5;
    const int b    = blockIdx.x * GROUPS + g;

    uint32_t* grp = smw + 2 * WPL_WORDS + g * GRP_WORDS;
    uint32_t* hhi = grp;                              // h hi plane [node][kword]
    uint32_t* hlo = grp + HPL_WORDS;                  // h lo plane
    float*    ps  = reinterpret_cast<float*>(grp + 2 * HPL_WORDS); // p [j][node]

    // ---------- init: W^T bf16 planes + zero h planes ----------
    for (int idx = tid; idx < 128 * 64; idx += 512) {
        int jr = idx >> 6;
        int k2 = idx & 63;
        int k  = 2 * k2;
        float w0 = gw[k * HDIM + jr];
        float w1 = gw[(k + 1) * HDIM + jr];
        float h0, l0, h1, l1;
        split_bf16(w0, h0, l0);
        split_bf16(w1, h1, l1);
        wth[jr * 68 + k2] = pack_bf16(h0, h1);
        wtl[jr * 68 + k2] = pack_bf16(l0, l1);
    }
    for (int i = tid; i < GROUPS * GRP_WORDS; i += 512)
        smw[2 * WPL_WORDS + i] = 0u;
    __syncthreads();

    // ---------- per-thread persistent state ----------
    float xi, xf, xo, xc;
    {
        const float4 v = reinterpret_cast<const float4*>(g_xg)[b * HDIM + ltid];
        float gbv = gb[ltid];
        xi = 0.5f * (v.x + gbv);
        xf = 0.5f * (v.y + gbv);
        xo = 0.5f * (v.z + gbv);
        xc = v.w + gbv;
    }
    float c[NNODES];
#pragma unroll
    for (int m = 0; m < NNODES; m++) c[m] = 0.f;

    // A-fragment ldmatrix bases: [plane][mt]
    const int lq  = lane >> 2;
    const int kw  = lane & 3;
    const int wof = wig * 32;
    uint32_t a_base[2][2];
    {
        int arow = (lane & 7) + ((lane >> 3) & 1) * 8;
        int acol = ((lane >> 4) & 1) * 4;
#pragma unroll
        for (int p = 0; p < 2; p++) {
            const uint32_t* pl = p ? wtl : wth;
#pragma unroll
            for (int mt = 0; mt < 2; mt++)
                a_base[p][mt] = smem_u32(pl + (wof + mt * 16 + arow) * 68 + acol);
        }
    }
    // B-fragment ldmatrix bases: [plane][nt]; x4 = {b0,b1} for 2 k-steps
    uint32_t b_base[2][3];
    {
        int brow  = lane & 7;
        int bhalf = lane >> 3;            // 0..3
#pragma unroll
        for (int p = 0; p < 2; p++) {
            const uint32_t* pl = p ? hlo : hhi;
#pragma unroll
            for (int nt = 0; nt < 3; nt++)
                b_base[p][nt] = smem_u32(pl + (nt * 8 + brow) * 68) + bhalf * 16;
        }
    }

    const int bar = g + 1;
    __nv_bfloat16* hhi_h = reinterpret_cast<__nv_bfloat16*>(hhi);
    __nv_bfloat16* hlo_h = reinterpret_cast<__nv_bfloat16*>(hlo);

    // phase stagger: groups drift anti-phase so HMMA and MUFU bursts overlap
    __nanosleep(g * 1200u);

    for (int t = 0; t < TSTEPS; t++) {
        // ---- mma phase: p^T(2mt x 3nt) = W^T(hi/lo) @ h(hi/lo), K=128 ----
        float acc[2][3][4];
#pragma unroll
        for (int mt = 0; mt < 2; mt++)
#pragma unroll
            for (int nt = 0; nt < 3; nt++)
#pragma unroll
                for (int q = 0; q < 4; q++) acc[mt][nt][q] = 0.f;

#pragma unroll
        for (int kp = 0; kp < 4; kp++) {          // pairs of k-steps
            uint32_t bh[3][4], bl[3][4];
#pragma unroll
            for (int nt = 0; nt < 3; nt++) {
                LDSM_X4(bh[nt][0], bh[nt][1], bh[nt][2], bh[nt][3],
                        b_base[0][nt] + kp * 64);
                LDSM_X4(bl[nt][0], bl[nt][1], bl[nt][2], bl[nt][3],
                        b_base[1][nt] + kp * 64);
            }
#pragma unroll
            for (int hf = 0; hf < 2; hf++) {      // kt = 2*kp + hf
                const uint32_t koff = (2 * kp + hf) * 32;
                uint32_t ah[2][4], al[2][4];
#pragma unroll
                for (int mt = 0; mt < 2; mt++) {
                    LDSM_X4(ah[mt][0], ah[mt][1], ah[mt][2], ah[mt][3],
                            a_base[0][mt] + koff);
                    LDSM_X4(al[mt][0], al[mt][1], al[mt][2], al[mt][3],
                            a_base[1][mt] + koff);
                }
#pragma unroll
                for (int nt = 0; nt < 3; nt++) {
                    uint32_t b0h = bh[nt][hf * 2], b1h = bh[nt][hf * 2 + 1];
                    uint32_t b0l = bl[nt][hf * 2], b1l = bl[nt][hf * 2 + 1];
#pragma unroll
                    for (int mt = 0; mt < 2; mt++) {
                        MMA_BF16(acc[mt][nt], ah[mt][0], ah[mt][1], ah[mt][2], ah[mt][3], b0h, b1h);
                        MMA_BF16(acc[mt][nt], ah[mt][0], ah[mt][1], ah[mt][2], ah[mt][3], b0l, b1l);
                        MMA_BF16(acc[mt][nt], al[mt][0], al[mt][1], al[mt][2], al[mt][3], b0h, b1h);
                    }
                }
            }
        }

        // ---- spill p fragments: ps[j][node], STS.64 pairs ----
#pragma unroll
        for (int mt = 0; mt < 2; mt++) {
            int j0 = wof + mt * 16 + lq;
            int j1 = j0 + 8;
#pragma unroll
            for (int nt = 0; nt < 3; nt++) {
                int n0 = nt * 8 + (kw << 1);
                *reinterpret_cast<float2*>(&ps[j0 * P_STRIDE + n0]) =
                    make_float2(acc[mt][nt][0], acc[mt][nt][1]);
                *reinterpret_cast<float2*>(&ps[j1 * P_STRIDE + n0]) =
                    make_float2(acc[mt][nt][2], acc[mt][nt][3]);
            }
        }
        asm volatile("bar.sync %0, 128;" :: "r"(bar) : "memory");

        // ---- combine + epilogue: thread owns column j = ltid ----
        float p[NNODES];
        {
            const float4* pv = reinterpret_cast<const float4*>(&ps[ltid * P_STRIDE]);
#pragma unroll
            for (int q = 0; q < 5; q++) {
                float4 v = pv[q];
                p[q * 4 + 0] = v.x; p[q * 4 + 1] = v.y;
                if (q * 4 + 2 < NNODES) p[q * 4 + 2] = v.z;
                if (q * 4 + 3 < NNODES) p[q * 4 + 3] = v.w;
            }
            float2 v2 = *reinterpret_cast<const float2*>(&ps[ltid * P_STRIDE + 20]);
            p[20] = v2.x; p[21] = v2.y;
        }

        // clique sums
        float S[5];
#pragma unroll
        for (int cq = 0; cq < 5; cq++) {
            float s = 0.f;
#pragma unroll
            for (int e = 0; e < 6; e++) {
                if (CLQ[cq][e] >= 0) {
                    const int n = CLQ[cq][e];
                    s = fmaf(DINV[n], p[n], s);
                }
            }
            S[cq] = s;
        }

        float* ob = out + (((size_t)b * TSTEPS + t) * NNODES) * HDIM + ltid;
#pragma unroll
        for (int m = 0; m < NNODES; m++) {
            float s = 0.f;
#pragma unroll
            for (int cq = 0; cq < 5; cq++)
                if ((CMASK[m] >> cq) & 1) s += S[cq];
            float gacc = DINV[m] * (s - CCNT[m] * DINV[m] * p[m]);

            float hd = 0.5f * gacc;
            float it = sig_h(xi + hd);
            float ft = sig_h(xf + hd);
            float ot = sig_h(xo + hd);
            float ct = tanha(xc + gacc);
            float cn = fmaf(ft, c[m], it * ct);
            c[m] = cn;
            float hv = ot * tanha(cn);
            ob[m * HDIM] = hv;
            float hh, hl;
            split_bf16(hv, hh, hl);
            hhi_h[m * 136 + ltid] = __float2bfloat16(hh);
            hlo_h[m * 136 + ltid] = __float2bfloat16(hl);
        }
        asm volatile("bar.sync %0, 128;" :: "r"(bar) : "memory");
    }
}

// -------------------- launch -------------------------------------------------
extern "C" void kernel_launch(void* const* d_in, const int* in_sizes, int n_in,
                              void* d_out, int out_size) {
    (void)in_sizes; (void)n_in; (void)out_size;
    const float* x     = (const float*)d_in[0];
    const float* wi_w  = (const float*)d_in[1];
    const float* wi_b  = (const float*)d_in[2];
    const float* wf_w  = (const float*)d_in[3];
    const float* wf_b  = (const float*)d_in[4];
    const float* wo_w  = (const float*)d_in[5];
    const float* wo_b  = (const float*)d_in[6];
    const float* wc_w  = (const float*)d_in[7];
    const float* wc_b  = (const float*)d_in[8];
    const float* gcn_w = (const float*)d_in[9];
    const float* gcn_b = (const float*)d_in[10];
    float* out = (float*)d_out;

    const int smem_bytes = TOT_WORDS * 4;   // 175 KB
    cudaFuncSetAttribute(fused_kernel,
                         cudaFuncAttributeMaxDynamicSharedMemorySize, smem_bytes);

    gate_kernel<<<dim3(BATCH / 16, 4), 128>>>(x, wi_w, wi_b, wf_w, wf_b,
                                              wo_w, wo_b, wc_w, wc_b);
    fused_kernel<<<BATCH / GROUPS, 512, smem_bytes>>>(gcn_w, gcn_b, out);
}

// round 11
// speedup vs baseline: 4.9007x; 1.0419x over previous
#include <cuda_runtime.h>
#include <cuda_bf16.h>
#include <cstdint>

// ---------------------------------------------------------------------------
// GraphConvLSTM on GB300 — Round 11: R10 with barrier diet.
//   p spill/reload is intra-warp (warp wig writes ps rows [32*wig,32*wig+32),
//   thread ltid reads row ltid of same warp) => bar.sync #1 -> __syncwarp().
//   One cross-warp barrier per step remains (h planes feed next step's mma).
// ---------------------------------------------------------------------------

#define BATCH   512
#define INDIM   256
#define HDIM    128
#define TSTEPS  100
#define NNODES  22
#define GROUPS  4

// smem word layout (4B words)
#define WPL_WORDS  (128 * 68)          // one W^T bf16 plane [j][kword], stride 68
#define HPL_WORDS  (24 * 68)           // one h bf16 plane [node][kword]
#define P_STRIDE   28                  // p row stride: 112B, 16B-aligned, cf-free
#define P_WORDS    (128 * P_STRIDE)
#define GRP_WORDS  (2 * HPL_WORDS + P_WORDS)              // 6848
#define TOT_WORDS  (2 * WPL_WORDS + GROUPS * GRP_WORDS)   // 44800 (175 KB)

// -------------------- scratch (device globals, no allocs) ------------------
__device__ float g_xg[BATCH * HDIM * 4];   // packed [b][j][gate i,f,o,c]

// -------------------- clique-factored adjacency ------------------------------
__device__ constexpr int CLQ[5][6] = {
    {0,2,5,8,11,-1}, {0,1,4,7,10,-1}, {0,3,6,9,12,15},
    {9,14,17,19,21,-1}, {9,13,16,18,20,-1}
};
__device__ constexpr int CMASK[22] = {
    7,2,1,4,2,1,4,2,1,28,2,1,4,16,8,4,16,8,16,8,16,8
};
__device__ constexpr float CCNT[22] = {
    3.f,1.f,1.f,1.f,1.f,1.f,1.f,1.f,1.f,3.f,1.f,1.f,1.f,1.f,1.f,1.f,1.f,1.f,1.f,1.f,1.f,1.f
};
__device__ constexpr float DINV[22] = {
    0.2773500979f, 0.5f, 0.5f, 0.4472135955f, 0.5f, 0.5f, 0.4472135955f, 0.5f, 0.5f,
    0.2773500979f, 0.5f, 0.5f, 0.4472135955f, 0.5f, 0.5f, 0.4472135955f,
    0.5f, 0.5f, 0.5f, 0.5f, 0.5f, 0.5f
};

// -------------------- helpers ------------------------------------------------
__device__ __forceinline__ uint32_t pack_bf16(float a, float b) {
    __nv_bfloat162 v = __floats2bfloat162_rn(a, b);
    return *reinterpret_cast<uint32_t*>(&v);
}
__device__ __forceinline__ void split_bf16(float f, float& hi, float& lo) {
    __nv_bfloat16 h = __float2bfloat16(f);
    hi = __bfloat162float(h);
    lo = f - hi;
}
__device__ __forceinline__ float tanha(float x) {
    float r;
    asm("tanh.approx.f32 %0, %1;" : "=f"(r) : "f"(x));
    return r;
}
__device__ __forceinline__ float sig_h(float a) {   // sigmoid(2a)
    return fmaf(0.5f, tanha(a), 0.5f);
}
__device__ __forceinline__ uint32_t smem_u32(const void* p) {
    return static_cast<uint32_t>(__cvta_generic_to_shared(p));
}

#define MMA_BF16(D, A0, A1, A2, A3, B0, B1)                                    \
    asm volatile(                                                              \
        "mma.sync.aligned.m16n8k16.row.col.f32.bf16.bf16.f32 "                 \
        "{%0,%1,%2,%3}, {%4,%5,%6,%7}, {%8,%9}, {%0,%1,%2,%3};"                \
        : "+f"((D)[0]), "+f"((D)[1]), "+f"((D)[2]), "+f"((D)[3])               \
        : "r"(A0), "r"(A1), "r"(A2), "r"(A3), "r"(B0), "r"(B1))

#define LDSM_X4(R0, R1, R2, R3, ADDR)                                          \
    asm volatile(                                                              \
        "ldmatrix.sync.aligned.m8n8.x4.shared.b16 {%0,%1,%2,%3}, [%4];"        \
        : "=r"(R0), "=r"(R1), "=r"(R2), "=r"(R3) : "r"(ADDR))

// -------------------- gate projection: packed xg ----------------------------
__global__ __launch_bounds__(128) void gate_kernel(
    const float* __restrict__ x,
    const float* __restrict__ wi, const float* __restrict__ bi,
    const float* __restrict__ wf, const float* __restrict__ bf,
    const float* __restrict__ wo, const float* __restrict__ bo,
    const float* __restrict__ wc, const float* __restrict__ bc)
{
    __shared__ float xs[16 * INDIM];
    __shared__ float ws[32 * 129];

    int tid  = threadIdx.x;
    int gate = blockIdx.y;
    const float* w    = (gate == 0) ? wi : (gate == 1) ? wf : (gate == 2) ? wo : wc;
    const float* bias = (gate == 0) ? bi : (gate == 1) ? bf : (gate == 2) ? bo : bc;
    int b0 = blockIdx.x * 16;

    for (int i = tid; i < 16 * INDIM; i += 128) xs[i] = x[b0 * INDIM + i];

    float acc[16];
#pragma unroll
    for (int bb = 0; bb < 16; bb++) acc[bb] = 0.f;

    for (int k0 = 0; k0 < INDIM; k0 += 32) {
        __syncthreads();
        for (int i = tid; i < 128 * 32; i += 128) {
            int j = i >> 5, k = i & 31;
            ws[k * 129 + j] = w[j * INDIM + k0 + k];
        }
        __syncthreads();
#pragma unroll 8
        for (int k = 0; k < 32; k++) {
            float wv = ws[k * 129 + tid];
#pragma unroll
            for (int bb = 0; bb < 16; bb++)
                acc[bb] += xs[bb * INDIM + k0 + k] * wv;
        }
    }
    float bv = bias[tid];
#pragma unroll
    for (int bb = 0; bb < 16; bb++)
        g_xg[((b0 + bb) * HDIM + tid) * 4 + gate] = acc[bb] + bv;
}

// -------------------- fused recurrence ---------------------------------------
__global__ __launch_bounds__(512, 1) void fused_kernel(
    const float* __restrict__ gw,
    const float* __restrict__ gb,
    float* __restrict__ out)
{
    extern __shared__ uint32_t smw[];
    uint32_t* wth = smw;                  // W^T hi plane [j][kword], stride 68
    uint32_t* wtl = smw + WPL_WORDS;      // W^T lo plane

    const int tid  = threadIdx.x;
    const int g    = tid >> 7;            // group 0..3
    const int ltid = tid & 127;           // column j in combine phase
    const int lane = tid & 31;
    const int wig  = ltid >> 5;
    const int b    = blockIdx.x * GROUPS + g;

    uint32_t* grp = smw + 2 * WPL_WORDS + g * GRP_WORDS;
    uint32_t* hhi = grp;                              // h hi plane [node][kword]
    uint32_t* hlo = grp + HPL_WORDS;                  // h lo plane
    float*    ps  = reinterpret_cast<float*>(grp + 2 * HPL_WORDS); // p [j][node]

    // ---------- init: W^T bf16 planes + zero h planes ----------
    for (int idx = tid; idx < 128 * 64; idx += 512) {
        int jr = idx >> 6;
        int k2 = idx & 63;
        int k  = 2 * k2;
        float w0 = gw[k * HDIM + jr];
        float w1 = gw[(k + 1) * HDIM + jr];
        float h0, l0, h1, l1;
        split_bf16(w0, h0, l0);
        split_bf16(w1, h1, l1);
        wth[jr * 68 + k2] = pack_bf16(h0, h1);
        wtl[jr * 68 + k2] = pack_bf16(l0, l1);
    }
    for (int i = tid; i < GROUPS * GRP_WORDS; i += 512)
        smw[2 * WPL_WORDS + i] = 0u;
    __syncthreads();

    // ---------- per-thread persistent state ----------
    float xi, xf, xo, xc;
    {
        const float4 v = reinterpret_cast<const float4*>(g_xg)[b * HDIM + ltid];
        float gbv = gb[ltid];
        xi = 0.5f * (v.x + gbv);
        xf = 0.5f * (v.y + gbv);
        xo = 0.5f * (v.z + gbv);
        xc = v.w + gbv;
    }
    float c[NNODES];
#pragma unroll
    for (int m = 0; m < NNODES; m++) c[m] = 0.f;

    // A-fragment ldmatrix bases: [plane][mt]
    const int lq  = lane >> 2;
    const int kw  = lane & 3;
    const int wof = wig * 32;
    uint32_t a_base[2][2];
    {
        int arow = (lane & 7) + ((lane >> 3) & 1) * 8;
        int acol = ((lane >> 4) & 1) * 4;
#pragma unroll
        for (int p = 0; p < 2; p++) {
            const uint32_t* pl = p ? wtl : wth;
#pragma unroll
            for (int mt = 0; mt < 2; mt++)
                a_base[p][mt] = smem_u32(pl + (wof + mt * 16 + arow) * 68 + acol);
        }
    }
    // B-fragment ldmatrix bases: [plane][nt]; x4 = {b0,b1} for 2 k-steps
    uint32_t b_base[2][3];
    {
        int brow  = lane & 7;
        int bhalf = lane >> 3;            // 0..3
#pragma unroll
        for (int p = 0; p < 2; p++) {
            const uint32_t* pl = p ? hlo : hhi;
#pragma unroll
            for (int nt = 0; nt < 3; nt++)
                b_base[p][nt] = smem_u32(pl + (nt * 8 + brow) * 68) + bhalf * 16;
        }
    }

    const int bar = g + 1;
    __nv_bfloat16* hhi_h = reinterpret_cast<__nv_bfloat16*>(hhi);
    __nv_bfloat16* hlo_h = reinterpret_cast<__nv_bfloat16*>(hlo);

    // phase stagger: groups drift anti-phase so HMMA and MUFU bursts overlap
    __nanosleep(g * 2000u);

    for (int t = 0; t < TSTEPS; t++) {
        // ---- mma phase: p^T(2mt x 3nt) = W^T(hi/lo) @ h(hi/lo), K=128 ----
        float acc[2][3][4];
#pragma unroll
        for (int mt = 0; mt < 2; mt++)
#pragma unroll
            for (int nt = 0; nt < 3; nt++)
#pragma unroll
                for (int q = 0; q < 4; q++) acc[mt][nt][q] = 0.f;

#pragma unroll
        for (int kp = 0; kp < 4; kp++) {          // pairs of k-steps
            uint32_t bh[3][4], bl[3][4];
#pragma unroll
            for (int nt = 0; nt < 3; nt++) {
                LDSM_X4(bh[nt][0], bh[nt][1], bh[nt][2], bh[nt][3],
                        b_base[0][nt] + kp * 64);
                LDSM_X4(bl[nt][0], bl[nt][1], bl[nt][2], bl[nt][3],
                        b_base[1][nt] + kp * 64);
            }
#pragma unroll
            for (int hf = 0; hf < 2; hf++) {      // kt = 2*kp + hf
                const uint32_t koff = (2 * kp + hf) * 32;
                uint32_t ah[2][4], al[2][4];
#pragma unroll
                for (int mt = 0; mt < 2; mt++) {
                    LDSM_X4(ah[mt][0], ah[mt][1], ah[mt][2], ah[mt][3],
                            a_base[0][mt] + koff);
                    LDSM_X4(al[mt][0], al[mt][1], al[mt][2], al[mt][3],
                            a_base[1][mt] + koff);
                }
#pragma unroll
                for (int nt = 0; nt < 3; nt++) {
                    uint32_t b0h = bh[nt][hf * 2], b1h = bh[nt][hf * 2 + 1];
                    uint32_t b0l = bl[nt][hf * 2], b1l = bl[nt][hf * 2 + 1];
#pragma unroll
                    for (int mt = 0; mt < 2; mt++) {
                        MMA_BF16(acc[mt][nt], ah[mt][0], ah[mt][1], ah[mt][2], ah[mt][3], b0h, b1h);
                        MMA_BF16(acc[mt][nt], ah[mt][0], ah[mt][1], ah[mt][2], ah[mt][3], b0l, b1l);
                        MMA_BF16(acc[mt][nt], al[mt][0], al[mt][1], al[mt][2], al[mt][3], b0h, b1h);
                    }
                }
            }
        }

        // ---- spill p fragments: ps[j][node] (intra-warp rows) ----
#pragma unroll
        for (int mt = 0; mt < 2; mt++) {
            int j0 = wof + mt * 16 + lq;
            int j1 = j0 + 8;
#pragma unroll
            for (int nt = 0; nt < 3; nt++) {
                int n0 = nt * 8 + (kw << 1);
                *reinterpret_cast<float2*>(&ps[j0 * P_STRIDE + n0]) =
                    make_float2(acc[mt][nt][0], acc[mt][nt][1]);
                *reinterpret_cast<float2*>(&ps[j1 * P_STRIDE + n0]) =
                    make_float2(acc[mt][nt][2], acc[mt][nt][3]);
            }
        }
        // p exchange is warp-local: warp wig wrote exactly rows [32*wig,32*wig+32)
        // and thread ltid (in warp wig) reads row ltid from that same range.
        __syncwarp();

        // ---- combine + epilogue: thread owns column j = ltid ----
        float p[NNODES];
        {
            const float4* pv = reinterpret_cast<const float4*>(&ps[ltid * P_STRIDE]);
#pragma unroll
            for (int q = 0; q < 5; q++) {
                float4 v = pv[q];
                p[q * 4 + 0] = v.x; p[q * 4 + 1] = v.y;
                if (q * 4 + 2 < NNODES) p[q * 4 + 2] = v.z;
                if (q * 4 + 3 < NNODES) p[q * 4 + 3] = v.w;
            }
            float2 v2 = *reinterpret_cast<const float2*>(&ps[ltid * P_STRIDE + 20]);
            p[20] = v2.x; p[21] = v2.y;
        }

        // clique sums
        float S[5];
#pragma unroll
        for (int cq = 0; cq < 5; cq++) {
            float s = 0.f;
#pragma unroll
            for (int e = 0; e < 6; e++) {
                if (CLQ[cq][e] >= 0) {
                    const int n = CLQ[cq][e];
                    s = fmaf(DINV[n], p[n], s);
                }
            }
            S[cq] = s;
        }

        float* ob = out + (((size_t)b * TSTEPS + t) * NNODES) * HDIM + ltid;
#pragma unroll
        for (int m = 0; m < NNODES; m++) {
            float s = 0.f;
#pragma unroll
            for (int cq = 0; cq < 5; cq++)
                if ((CMASK[m] >> cq) & 1) s += S[cq];
            float gacc = DINV[m] * (s - CCNT[m] * DINV[m] * p[m]);

            float hd = 0.5f * gacc;
            float it = sig_h(xi + hd);
            float ft = sig_h(xf + hd);
            float ot = sig_h(xo + hd);
            float ct = tanha(xc + gacc);
            float cn = fmaf(ft, c[m], it * ct);
            c[m] = cn;
            float hv = ot * tanha(cn);
            ob[m * HDIM] = hv;
            float hh, hl;
            split_bf16(hv, hh, hl);
            hhi_h[m * 136 + ltid] = __float2bfloat16(hh);
            hlo_h[m * 136 + ltid] = __float2bfloat16(hl);
        }
        // h planes are read cross-warp by next step's B ldmatrix: full group sync
        asm volatile("bar.sync %0, 128;" :: "r"(bar) : "memory");
    }
}

// -------------------- launch -------------------------------------------------
extern "C" void kernel_launch(void* const* d_in, const int* in_sizes, int n_in,
                              void* d_out, int out_size) {
    (void)in_sizes; (void)n_in; (void)out_size;
    const float* x     = (const float*)d_in[0];
    const float* wi_w  = (const float*)d_in[1];
    const float* wi_b  = (const float*)d_in[2];
    const float* wf_w  = (const float*)d_in[3];
    const float* wf_b  = (const float*)d_in[4];
    const float* wo_w  = (const float*)d_in[5];
    const float* wo_b  = (const float*)d_in[6];
    const float* wc_w  = (const float*)d_in[7];
    const float* wc_b  = (const float*)d_in[8];
    const float* gcn_w = (const float*)d_in[9];
    const float* gcn_b = (const float*)d_in[10];
    float* out = (float*)d_out;

    const int smem_bytes = TOT_WORDS * 4;   // 175 KB
    cudaFuncSetAttribute(fused_kernel,
                         cudaFuncAttributeMaxDynamicSharedMemorySize, smem_bytes);

    gate_kernel<<<dim3(BATCH / 16, 4), 128>>>(x, wi_w, wi_b, wf_w, wf_b,
                                              wo_w, wo_b, wc_w, wc_b);
    fused_kernel<<<BATCH / GROUPS, 512, smem_bytes>>>(gcn_w, gcn_b, out);
}

// round 12
// speedup vs baseline: 4.9228x; 1.0045x over previous
#include <cuda_runtime.h>
#include <cuda_bf16.h>
#include <cstdint>

// ---------------------------------------------------------------------------
// GraphConvLSTM on GB300 — Round 12: R11 + double-buffered h planes.
//   Fixes the R11 WAR race (epilogue h-writes vs in-flight B ldmatrix reads)
//   without re-adding the mid-step barrier: step t reads h buf (t&1),
//   epilogue writes h buf ((t+1)&1); one bar.sync per step (RAW only).
// ---------------------------------------------------------------------------

#define BATCH   512
#define INDIM   256
#define HDIM    128
#define TSTEPS  100
#define NNODES  22
#define GROUPS  4

// smem word layout (4B words)
#define WPL_WORDS  (128 * 68)          // one W^T bf16 plane [j][kword], stride 68
#define HPL_WORDS  (24 * 68)           // one h bf16 plane [node][kword]
#define HBUF_BYTES (2 * HPL_WORDS * 4) // hi+lo pair, one buffer (13056 B)
#define P_STRIDE   28                  // p row stride: 112B, 16B-aligned, cf-free
#define P_WORDS    (128 * P_STRIDE)
#define GRP_WORDS  (4 * HPL_WORDS + P_WORDS)              // 10112
#define TOT_WORDS  (2 * WPL_WORDS + GROUPS * GRP_WORDS)   // 57856 (226 KB)

// -------------------- scratch (device globals, no allocs) ------------------
__device__ float g_xg[BATCH * HDIM * 4];   // packed [b][j][gate i,f,o,c]

// -------------------- clique-factored adjacency ------------------------------
__device__ constexpr int CLQ[5][6] = {
    {0,2,5,8,11,-1}, {0,1,4,7,10,-1}, {0,3,6,9,12,15},
    {9,14,17,19,21,-1}, {9,13,16,18,20,-1}
};
__device__ constexpr int CMASK[22] = {
    7,2,1,4,2,1,4,2,1,28,2,1,4,16,8,4,16,8,16,8,16,8
};
__device__ constexpr float CCNT[22] = {
    3.f,1.f,1.f,1.f,1.f,1.f,1.f,1.f,1.f,3.f,1.f,1.f,1.f,1.f,1.f,1.f,1.f,1.f,1.f,1.f,1.f,1.f
};
__device__ constexpr float DINV[22] = {
    0.2773500979f, 0.5f, 0.5f, 0.4472135955f, 0.5f, 0.5f, 0.4472135955f, 0.5f, 0.5f,
    0.2773500979f, 0.5f, 0.5f, 0.4472135955f, 0.5f, 0.5f, 0.4472135955f,
    0.5f, 0.5f, 0.5f, 0.5f, 0.5f, 0.5f
};

// -------------------- helpers ------------------------------------------------
__device__ __forceinline__ uint32_t pack_bf16(float a, float b) {
    __nv_bfloat162 v = __floats2bfloat162_rn(a, b);
    return *reinterpret_cast<uint32_t*>(&v);
}
__device__ __forceinline__ void split_bf16(float f, float& hi, float& lo) {
    __nv_bfloat16 h = __float2bfloat16(f);
    hi = __bfloat162float(h);
    lo = f - hi;
}
__device__ __forceinline__ float tanha(float x) {
    float r;
    asm("tanh.approx.f32 %0, %1;" : "=f"(r) : "f"(x));
    return r;
}
__device__ __forceinline__ float sig_h(float a) {   // sigmoid(2a)
    return fmaf(0.5f, tanha(a), 0.5f);
}
__device__ __forceinline__ uint32_t smem_u32(const void* p) {
    return static_cast<uint32_t>(__cvta_generic_to_shared(p));
}

#define MMA_BF16(D, A0, A1, A2, A3, B0, B1)                                    \
    asm volatile(                                                              \
        "mma.sync.aligned.m16n8k16.row.col.f32.bf16.bf16.f32 "                 \
        "{%0,%1,%2,%3}, {%4,%5,%6,%7}, {%8,%9}, {%0,%1,%2,%3};"                \
        : "+f"((D)[0]), "+f"((D)[1]), "+f"((D)[2]), "+f"((D)[3])               \
        : "r"(A0), "r"(A1), "r"(A2), "r"(A3), "r"(B0), "r"(B1))

#define LDSM_X4(R0, R1, R2, R3, ADDR)                                          \
    asm volatile(                                                              \
        "ldmatrix.sync.aligned.m8n8.x4.shared.b16 {%0,%1,%2,%3}, [%4];"        \
        : "=r"(R0), "=r"(R1), "=r"(R2), "=r"(R3) : "r"(ADDR))

// -------------------- gate projection: packed xg ----------------------------
__global__ __launch_bounds__(128) void gate_kernel(
    const float* __restrict__ x,
    const float* __restrict__ wi, const float* __restrict__ bi,
    const float* __restrict__ wf, const float* __restrict__ bf,
    const float* __restrict__ wo, const float* __restrict__ bo,
    const float* __restrict__ wc, const float* __restrict__ bc)
{
    __shared__ float xs[16 * INDIM];
    __shared__ float ws[32 * 129];

    int tid  = threadIdx.x;
    int gate = blockIdx.y;
    const float* w    = (gate == 0) ? wi : (gate == 1) ? wf : (gate == 2) ? wo : wc;
    const float* bias = (gate == 0) ? bi : (gate == 1) ? bf : (gate == 2) ? bo : bc;
    int b0 = blockIdx.x * 16;

    for (int i = tid; i < 16 * INDIM; i += 128) xs[i] = x[b0 * INDIM + i];

    float acc[16];
#pragma unroll
    for (int bb = 0; bb < 16; bb++) acc[bb] = 0.f;

    for (int k0 = 0; k0 < INDIM; k0 += 32) {
        __syncthreads();
        for (int i = tid; i < 128 * 32; i += 128) {
            int j = i >> 5, k = i & 31;
            ws[k * 129 + j] = w[j * INDIM + k0 + k];
        }
        __syncthreads();
#pragma unroll 8
        for (int k = 0; k < 32; k++) {
            float wv = ws[k * 129 + tid];
#pragma unroll
            for (int bb = 0; bb < 16; bb++)
                acc[bb] += xs[bb * INDIM + k0 + k] * wv;
        }
    }
    float bv = bias[tid];
#pragma unroll
    for (int bb = 0; bb < 16; bb++)
        g_xg[((b0 + bb) * HDIM + tid) * 4 + gate] = acc[bb] + bv;
}

// -------------------- fused recurrence ---------------------------------------
__global__ __launch_bounds__(512, 1) void fused_kernel(
    const float* __restrict__ gw,
    const float* __restrict__ gb,
    float* __restrict__ out)
{
    extern __shared__ uint32_t smw[];
    uint32_t* wth = smw;                  // W^T hi plane [j][kword], stride 68
    uint32_t* wtl = smw + WPL_WORDS;      // W^T lo plane

    const int tid  = threadIdx.x;
    const int g    = tid >> 7;            // group 0..3
    const int ltid = tid & 127;           // column j in combine phase
    const int lane = tid & 31;
    const int wig  = ltid >> 5;
    const int b    = blockIdx.x * GROUPS + g;

    // group layout: [hhi0|hlo0|hhi1|hlo1|ps]
    uint32_t* grp  = smw + 2 * WPL_WORDS + g * GRP_WORDS;
    uint32_t* hbuf = grp;                                   // 4 h planes
    float*    ps   = reinterpret_cast<float*>(grp + 4 * HPL_WORDS);

    // ---------- init: W^T bf16 planes + zero h buffers ----------
    for (int idx = tid; idx < 128 * 64; idx += 512) {
        int jr = idx >> 6;
        int k2 = idx & 63;
        int k  = 2 * k2;
        float w0 = gw[k * HDIM + jr];
        float w1 = gw[(k + 1) * HDIM + jr];
        float h0, l0, h1, l1;
        split_bf16(w0, h0, l0);
        split_bf16(w1, h1, l1);
        wth[jr * 68 + k2] = pack_bf16(h0, h1);
        wtl[jr * 68 + k2] = pack_bf16(l0, l1);
    }
    for (int i = tid; i < GROUPS * GRP_WORDS; i += 512)
        smw[2 * WPL_WORDS + i] = 0u;
    __syncthreads();

    // ---------- per-thread persistent state ----------
    float xi, xf, xo, xc;
    {
        const float4 v = reinterpret_cast<const float4*>(g_xg)[b * HDIM + ltid];
        float gbv = gb[ltid];
        xi = 0.5f * (v.x + gbv);
        xf = 0.5f * (v.y + gbv);
        xo = 0.5f * (v.z + gbv);
        xc = v.w + gbv;
    }
    float c[NNODES];
#pragma unroll
    for (int m = 0; m < NNODES; m++) c[m] = 0.f;

    // A-fragment ldmatrix bases: [plane][mt]
    const int lq  = lane >> 2;
    const int kw  = lane & 3;
    const int wof = wig * 32;
    uint32_t a_base[2][2];
    {
        int arow = (lane & 7) + ((lane >> 3) & 1) * 8;
        int acol = ((lane >> 4) & 1) * 4;
#pragma unroll
        for (int p = 0; p < 2; p++) {
            const uint32_t* pl = p ? wtl : wth;
#pragma unroll
            for (int mt = 0; mt < 2; mt++)
                a_base[p][mt] = smem_u32(pl + (wof + mt * 16 + arow) * 68 + acol);
        }
    }
    // B-fragment ldmatrix bases for buffer 0: [plane][nt]; buffer 1 = +HBUF_BYTES
    uint32_t b_base[2][3];
    {
        int brow  = lane & 7;
        int bhalf = lane >> 3;            // 0..3
#pragma unroll
        for (int p = 0; p < 2; p++) {
            const uint32_t* pl = hbuf + p * HPL_WORDS;   // hhi0 / hlo0
#pragma unroll
            for (int nt = 0; nt < 3; nt++)
                b_base[p][nt] = smem_u32(pl + (nt * 8 + brow) * 68) + bhalf * 16;
        }
    }

    const int bar = g + 1;

    // phase stagger: groups drift anti-phase so HMMA and MUFU bursts overlap
    __nanosleep(g * 2000u);

    for (int t = 0; t < TSTEPS; t++) {
        const uint32_t rbuf = (uint32_t)(t & 1) * HBUF_BYTES;      // read buffer
        uint32_t* whbuf = hbuf + ((t + 1) & 1) * 2 * HPL_WORDS;    // write buffer
        __nv_bfloat16* hhi_w = reinterpret_cast<__nv_bfloat16*>(whbuf);
        __nv_bfloat16* hlo_w = reinterpret_cast<__nv_bfloat16*>(whbuf + HPL_WORDS);

        // ---- mma phase: p^T(2mt x 3nt) = W^T(hi/lo) @ h(hi/lo), K=128 ----
        float acc[2][3][4];
#pragma unroll
        for (int mt = 0; mt < 2; mt++)
#pragma unroll
            for (int nt = 0; nt < 3; nt++)
#pragma unroll
                for (int q = 0; q < 4; q++) acc[mt][nt][q] = 0.f;

#pragma unroll
        for (int kp = 0; kp < 4; kp++) {          // pairs of k-steps
            uint32_t bh[3][4], bl[3][4];
#pragma unroll
            for (int nt = 0; nt < 3; nt++) {
                LDSM_X4(bh[nt][0], bh[nt][1], bh[nt][2], bh[nt][3],
                        b_base[0][nt] + rbuf + kp * 64);
                LDSM_X4(bl[nt][0], bl[nt][1], bl[nt][2], bl[nt][3],
                        b_base[1][nt] + rbuf + kp * 64);
            }
#pragma unroll
            for (int hf = 0; hf < 2; hf++) {      // kt = 2*kp + hf
                const uint32_t koff = (2 * kp + hf) * 32;
                uint32_t ah[2][4], al[2][4];
#pragma unroll
                for (int mt = 0; mt < 2; mt++) {
                    LDSM_X4(ah[mt][0], ah[mt][1], ah[mt][2], ah[mt][3],
                            a_base[0][mt] + koff);
                    LDSM_X4(al[mt][0], al[mt][1], al[mt][2], al[mt][3],
                            a_base[1][mt] + koff);
                }
#pragma unroll
                for (int nt = 0; nt < 3; nt++) {
                    uint32_t b0h = bh[nt][hf * 2], b1h = bh[nt][hf * 2 + 1];
                    uint32_t b0l = bl[nt][hf * 2], b1l = bl[nt][hf * 2 + 1];
#pragma unroll
                    for (int mt = 0; mt < 2; mt++) {
                        MMA_BF16(acc[mt][nt], ah[mt][0], ah[mt][1], ah[mt][2], ah[mt][3], b0h, b1h);
                        MMA_BF16(acc[mt][nt], ah[mt][0], ah[mt][1], ah[mt][2], ah[mt][3], b0l, b1l);
                        MMA_BF16(acc[mt][nt], al[mt][0], al[mt][1], al[mt][2], al[mt][3], b0h, b1h);
                    }
                }
            }
        }

        // ---- spill p fragments: ps[j][node] (intra-warp rows) ----
#pragma unroll
        for (int mt = 0; mt < 2; mt++) {
            int j0 = wof + mt * 16 + lq;
            int j1 = j0 + 8;
#pragma unroll
            for (int nt = 0; nt < 3; nt++) {
                int n0 = nt * 8 + (kw << 1);
                *reinterpret_cast<float2*>(&ps[j0 * P_STRIDE + n0]) =
                    make_float2(acc[mt][nt][0], acc[mt][nt][1]);
                *reinterpret_cast<float2*>(&ps[j1 * P_STRIDE + n0]) =
                    make_float2(acc[mt][nt][2], acc[mt][nt][3]);
            }
        }
        // p exchange is warp-local (warp wig owns ps rows [32*wig, 32*wig+32))
        __syncwarp();

        // ---- combine + epilogue: thread owns column j = ltid ----
        float p[NNODES];
        {
            const float4* pv = reinterpret_cast<const float4*>(&ps[ltid * P_STRIDE]);
#pragma unroll
            for (int q = 0; q < 5; q++) {
                float4 v = pv[q];
                p[q * 4 + 0] = v.x; p[q * 4 + 1] = v.y;
                if (q * 4 + 2 < NNODES) p[q * 4 + 2] = v.z;
                if (q * 4 + 3 < NNODES) p[q * 4 + 3] = v.w;
            }
            float2 v2 = *reinterpret_cast<const float2*>(&ps[ltid * P_STRIDE + 20]);
            p[20] = v2.x; p[21] = v2.y;
        }

        // clique sums
        float S[5];
#pragma unroll
        for (int cq = 0; cq < 5; cq++) {
            float s = 0.f;
#pragma unroll
            for (int e = 0; e < 6; e++) {
                if (CLQ[cq][e] >= 0) {
                    const int n = CLQ[cq][e];
                    s = fmaf(DINV[n], p[n], s);
                }
            }
            S[cq] = s;
        }

        float* ob = out + (((size_t)b * TSTEPS + t) * NNODES) * HDIM + ltid;
#pragma unroll
        for (int m = 0; m < NNODES; m++) {
            float s = 0.f;
#pragma unroll
            for (int cq = 0; cq < 5; cq++)
                if ((CMASK[m] >> cq) & 1) s += S[cq];
            float gacc = DINV[m] * (s - CCNT[m] * DINV[m] * p[m]);

            float hd = 0.5f * gacc;
            float it = sig_h(xi + hd);
            float ft = sig_h(xf + hd);
            float ot = sig_h(xo + hd);
            float ct = tanha(xc + gacc);
            float cn = fmaf(ft, c[m], it * ct);
            c[m] = cn;
            float hv = ot * tanha(cn);
            ob[m * HDIM] = hv;
            float hh, hl;
            split_bf16(hv, hh, hl);
            hhi_w[m * 136 + ltid] = __float2bfloat16(hh);
            hlo_w[m * 136 + ltid] = __float2bfloat16(hl);
        }
        // RAW: step-t h writes (buf (t+1)&1) visible to step-t+1 B reads
        asm volatile("bar.sync %0, 128;" :: "r"(bar) : "memory");
    }
}

// -------------------- launch -------------------------------------------------
extern "C" void kernel_launch(void* const* d_in, const int* in_sizes, int n_in,
                              void* d_out, int out_size) {
    (void)in_sizes; (void)n_in; (void)out_size;
    const float* x     = (const float*)d_in[0];
    const float* wi_w  = (const float*)d_in[1];
    const float* wi_b  = (const float*)d_in[2];
    const float* wf_w  = (const float*)d_in[3];
    const float* wf_b  = (const float*)d_in[4];
    const float* wo_w  = (const float*)d_in[5];
    const float* wo_b  = (const float*)d_in[6];
    const float* wc_w  = (const float*)d_in[7];
    const float* wc_b  = (const float*)d_in[8];
    const float* gcn_w = (const float*)d_in[9];
    const float* gcn_b = (const float*)d_in[10];
    float* out = (float*)d_out;

    const int smem_bytes = TOT_WORDS * 4;   // 231,424 B (~226 KB)
    cudaFuncSetAttribute(fused_kernel,
                         cudaFuncAttributeMaxDynamicSharedMemorySize, smem_bytes);

    gate_kernel<<<dim3(BATCH / 16, 4), 128>>>(x, wi_w, wi_b, wf_w, wf_b,
                                              wo_w, wo_b, wc_w, wc_b);
    fused_kernel<<<BATCH / GROUPS, 512, smem_bytes>>>(gcn_w, gcn_b, out);
}